// round 1
// baseline (speedup 1.0000x reference)
#include <cuda_runtime.h>

// ---------------- problem constants ----------------
#define B_SZ   8
#define T_LEN  4096
#define D_INP  256
#define D_OUTP 256
#define N_ST   512
#define M_TOT  (B_SZ * T_LEN)      // 32768
#define NBU    (2 * N_ST)          // 1024 (real | imag)
#define CHUNK  128
#define NCHUNK (T_LEN / CHUNK)     // 32

// ---------------- device scratch (no allocs allowed) ----------------
__device__ float  g_Bs[NBU * D_INP];              // gamma-scaled [B_real; B_imag], [1024][256]
__device__ float  g_W1[D_OUTP * NBU];             // [256][1024] = [2*C_real | -2*C_imag]
__device__ float  g_Bu[(size_t)M_TOT * NBU];      // 134 MB
__device__ float  g_X [(size_t)M_TOT * NBU];      // 134 MB
__device__ float2 g_lam [N_ST];
__device__ float2 g_lamL[N_ST];                   // lam^CHUNK
__device__ float2 g_F    [B_SZ * NCHUNK * N_ST];  // chunk-local finals
__device__ float2 g_carry[B_SZ * NCHUNK * N_ST];  // chunk carry-in states

// ---------------- small setup kernels ----------------
__global__ void k_setup(const float* __restrict__ nu_log,
                        const float* __restrict__ theta_log) {
    int n = blockIdx.x * blockDim.x + threadIdx.x;
    if (n >= N_ST) return;
    float lm = expf(-expf(nu_log[n]));
    float th = expf(theta_log[n]);
    float2 lam = make_float2(lm * cosf(th), lm * sinf(th));
    g_lam[n] = lam;
    // lam^128 by 7 squarings
    float2 p = lam;
#pragma unroll
    for (int i = 0; i < 7; i++) {
        float2 q;
        q.x = p.x * p.x - p.y * p.y;
        q.y = 2.0f * p.x * p.y;
        p = q;
    }
    g_lamL[n] = p;
}

__global__ void k_scaleB(const float* __restrict__ gamma_log,
                         const float* __restrict__ Br,
                         const float* __restrict__ Bi) {
    int idx = blockIdx.x * blockDim.x + threadIdx.x;
    if (idx >= NBU * D_INP) return;
    int nn = idx / D_INP, i = idx % D_INP;
    int n = (nn < N_ST) ? nn : nn - N_ST;
    float g = expf(gamma_log[n]);
    float v = (nn < N_ST) ? Br[n * D_INP + i] : Bi[n * D_INP + i];
    g_Bs[idx] = g * v;
}

__global__ void k_buildW1(const float* __restrict__ Cr,
                          const float* __restrict__ Ci) {
    int idx = blockIdx.x * blockDim.x + threadIdx.x;
    if (idx >= D_OUTP * NBU) return;
    int o = idx / NBU, n = idx % NBU;
    g_W1[idx] = (n < N_ST) ? 2.0f * Cr[o * N_ST + n]
                           : -2.0f * Ci[o * N_ST + (n - N_ST)];
}

// ---------------- fp32 NT SGEMM: C[m,n] = sum_k A[m,k]*B[n,k] ----------------
// A: MxK row-major, B: NxK row-major, C: MxN row-major.
// 128x128 tile, BK=8, 256 threads, 8x8 per thread (4+4 split).
template <bool ACCUM>
__global__ __launch_bounds__(256)
void sgemm_nt(const float* __restrict__ A, const float* __restrict__ Bm,
              float* __restrict__ C, int M, int N, int K) {
    __shared__ float As[8][128];
    __shared__ float Bs[8][128];

    const int tid = threadIdx.x;
    const int m0 = blockIdx.y * 128;
    const int n0 = blockIdx.x * 128;

    const int lr = tid >> 1;          // 0..127
    const int lc = (tid & 1) * 4;     // 0 or 4
    const float* Ap = A + (size_t)(m0 + lr) * K + lc;
    const float* Bp = Bm + (size_t)(n0 + lr) * K + lc;

    const int tx = tid & 15;          // 0..15
    const int ty = tid >> 4;          // 0..15

    float acc[8][8];
#pragma unroll
    for (int i = 0; i < 8; i++)
#pragma unroll
        for (int j = 0; j < 8; j++) acc[i][j] = 0.0f;

    float4 av = *(const float4*)(Ap);
    float4 bv = *(const float4*)(Bp);

    for (int k0 = 0; k0 < K; k0 += 8) {
        __syncthreads();
        As[lc + 0][lr] = av.x; As[lc + 1][lr] = av.y;
        As[lc + 2][lr] = av.z; As[lc + 3][lr] = av.w;
        Bs[lc + 0][lr] = bv.x; Bs[lc + 1][lr] = bv.y;
        Bs[lc + 2][lr] = bv.z; Bs[lc + 3][lr] = bv.w;
        __syncthreads();

        if (k0 + 8 < K) {
            av = *(const float4*)(Ap + k0 + 8);
            bv = *(const float4*)(Bp + k0 + 8);
        }

#pragma unroll
        for (int kk = 0; kk < 8; kk++) {
            float a[8], b[8];
            *(float4*)(a)     = *(const float4*)(&As[kk][ty * 4]);
            *(float4*)(a + 4) = *(const float4*)(&As[kk][ty * 4 + 64]);
            *(float4*)(b)     = *(const float4*)(&Bs[kk][tx * 4]);
            *(float4*)(b + 4) = *(const float4*)(&Bs[kk][tx * 4 + 64]);
#pragma unroll
            for (int i = 0; i < 8; i++)
#pragma unroll
                for (int j = 0; j < 8; j++) acc[i][j] += a[i] * b[j];
        }
    }

#pragma unroll
    for (int ii = 0; ii < 2; ii++) {
#pragma unroll
        for (int i = 0; i < 4; i++) {
            int row = m0 + ii * 64 + ty * 4 + i;
#pragma unroll
            for (int jj = 0; jj < 2; jj++) {
                int col = n0 + jj * 64 + tx * 4;
                float* cp = C + (size_t)row * N + col;
                float4 v = make_float4(acc[ii * 4 + i][jj * 4 + 0],
                                       acc[ii * 4 + i][jj * 4 + 1],
                                       acc[ii * 4 + i][jj * 4 + 2],
                                       acc[ii * 4 + i][jj * 4 + 3]);
                if (ACCUM) {
                    float4 o = *(const float4*)cp;
                    v.x += o.x; v.y += o.y; v.z += o.z; v.w += o.w;
                }
                *(float4*)cp = v;
            }
        }
    }
}

// ---------------- chunked complex scan ----------------
// Pass 1: per (b, chunk, n) scan with zero init -> chunk final F.
__global__ void k_scan_final() {
    int id = blockIdx.x * blockDim.x + threadIdx.x;
    if (id >= B_SZ * NCHUNK * N_ST) return;
    int n = id & (N_ST - 1);
    int c = (id >> 9) & (NCHUNK - 1);
    int b = id >> 14;
    float2 lam = g_lam[n];
    float xr = 0.0f, xi = 0.0f;
    const float* base = g_Bu + ((size_t)(b * T_LEN + c * CHUNK)) * NBU + n;
#pragma unroll 4
    for (int t = 0; t < CHUNK; t++) {
        float br = base[(size_t)t * NBU];
        float bi = base[(size_t)t * NBU + N_ST];
        float nxr = lam.x * xr - lam.y * xi + br;
        float nxi = lam.x * xi + lam.y * xr + bi;
        xr = nxr; xi = nxi;
    }
    g_F[id] = make_float2(xr, xi);
}

// Pass 2: per (b, n) chunk-level recurrence S_c = lam^L * S_{c-1} + F_c;
// carry[c] = S_{c-1}  (state entering chunk c).
__global__ void k_chunk_prefix() {
    int id = blockIdx.x * blockDim.x + threadIdx.x;
    if (id >= B_SZ * N_ST) return;
    int n = id & (N_ST - 1);
    int b = id >> 9;
    float2 lamL = g_lamL[n];
    float sr = 0.0f, si = 0.0f;
#pragma unroll
    for (int c = 0; c < NCHUNK; c++) {
        int idx = (b * NCHUNK + c) * N_ST + n;
        g_carry[idx] = make_float2(sr, si);
        float2 f = g_F[idx];
        float nsr = lamL.x * sr - lamL.y * si + f.x;
        float nsi = lamL.x * si + lamL.y * sr + f.y;
        sr = nsr; si = nsi;
    }
}

// Pass 3: re-scan each chunk seeded with its carry, write full X.
__global__ void k_scan_write() {
    int id = blockIdx.x * blockDim.x + threadIdx.x;
    if (id >= B_SZ * NCHUNK * N_ST) return;
    int n = id & (N_ST - 1);
    int c = (id >> 9) & (NCHUNK - 1);
    int b = id >> 14;
    float2 lam = g_lam[n];
    float2 cin = g_carry[id];
    float xr = cin.x, xi = cin.y;
    const float* base = g_Bu + ((size_t)(b * T_LEN + c * CHUNK)) * NBU + n;
    float* xbase = g_X + ((size_t)(b * T_LEN + c * CHUNK)) * NBU + n;
#pragma unroll 4
    for (int t = 0; t < CHUNK; t++) {
        float br = base[(size_t)t * NBU];
        float bi = base[(size_t)t * NBU + N_ST];
        float nxr = lam.x * xr - lam.y * xi + br;
        float nxi = lam.x * xi + lam.y * xr + bi;
        xr = nxr; xi = nxi;
        xbase[(size_t)t * NBU]        = xr;
        xbase[(size_t)t * NBU + N_ST] = xi;
    }
}

// ---------------- launch ----------------
extern "C" void kernel_launch(void* const* d_in, const int* in_sizes, int n_in,
                              void* d_out, int out_size) {
    const float* u_in      = (const float*)d_in[0];
    const float* nu_log    = (const float*)d_in[1];
    const float* theta_log = (const float*)d_in[2];
    const float* gamma_log = (const float*)d_in[3];
    const float* B_real    = (const float*)d_in[4];
    const float* B_imag    = (const float*)d_in[5];
    const float* C_real    = (const float*)d_in[6];
    const float* C_imag    = (const float*)d_in[7];
    const float* Dm        = (const float*)d_in[8];
    float* y = (float*)d_out;

    float* bs; cudaGetSymbolAddress((void**)&bs, g_Bs);
    float* w1; cudaGetSymbolAddress((void**)&w1, g_W1);
    float* bu; cudaGetSymbolAddress((void**)&bu, g_Bu);
    float* xb; cudaGetSymbolAddress((void**)&xb, g_X);

    // setup
    k_setup<<<2, 256>>>(nu_log, theta_log);
    k_scaleB<<<(NBU * D_INP + 255) / 256, 256>>>(gamma_log, B_real, B_imag);
    k_buildW1<<<(D_OUTP * NBU + 255) / 256, 256>>>(C_real, C_imag);

    // GEMM 1: Bu[M, 1024] = u @ Bs^T
    {
        dim3 grid(NBU / 128, M_TOT / 128);
        sgemm_nt<false><<<grid, 256>>>(u_in, bs, bu, M_TOT, NBU, D_INP);
    }

    // scan
    k_scan_final<<<(B_SZ * NCHUNK * N_ST + 255) / 256, 256>>>();
    k_chunk_prefix<<<(B_SZ * N_ST + 255) / 256, 256>>>();
    k_scan_write<<<(B_SZ * NCHUNK * N_ST + 255) / 256, 256>>>();

    // GEMM 2: y = X @ W1^T   (writes all of y)
    {
        dim3 grid(D_OUTP / 128, M_TOT / 128);
        sgemm_nt<false><<<grid, 256>>>(xb, w1, y, M_TOT, D_OUTP, NBU);
    }
    // GEMM 3: y += u @ D^T
    {
        dim3 grid(D_OUTP / 128, M_TOT / 128);
        sgemm_nt<true><<<grid, 256>>>(u_in, Dm, y, M_TOT, D_OUTP, D_INP);
    }
}

// round 3
// speedup vs baseline: 1.6463x; 1.6463x over previous
#include <cuda_runtime.h>
#include <cuda_bf16.h>
#include <cstdint>

// ---------------- problem constants ----------------
#define B_SZ   8
#define T_LEN  4096
#define D_INP  256
#define D_OUTP 256
#define N_ST   512
#define M_TOT  (B_SZ * T_LEN)      // 32768
#define NBU    (2 * N_ST)          // 1024
#define KCAT   (NBU + D_INP)       // 1280
#define CHUNK  128
#define NCHUNK (T_LEN / CHUNK)     // 32

// ---------------- device scratch ----------------
__device__ __nv_bfloat16 g_A2h[(size_t)M_TOT * KCAT];   // [X_hi | u_hi]
__device__ __nv_bfloat16 g_A2l[(size_t)M_TOT * KCAT];   // [X_lo | u_lo]
__device__ float         g_Bu[(size_t)M_TOT * NBU];     // fp32 driving term
__device__ __nv_bfloat16 g_B1h[NBU * D_INP];            // gamma-scaled B, hi
__device__ __nv_bfloat16 g_B1l[NBU * D_INP];
__device__ __nv_bfloat16 g_W2h[D_OUTP * KCAT];          // [2Cr | -2Ci | D], hi
__device__ __nv_bfloat16 g_W2l[D_OUTP * KCAT];
__device__ float2 g_lam [N_ST];
__device__ float2 g_lamL[N_ST];
__device__ float2 g_F    [B_SZ * NCHUNK * N_ST];
__device__ float2 g_carry[B_SZ * NCHUNK * N_ST];

// ---------------- helpers ----------------
__device__ __forceinline__ uint32_t smem_u32(const void* p) {
    uint32_t a;
    asm("{ .reg .u64 t; cvta.to.shared.u64 t, %1; cvt.u32.u64 %0, t; }" : "=r"(a) : "l"(p));
    return a;
}

#define CP_ASYNC16(dst, src) \
    asm volatile("cp.async.cg.shared.global [%0], [%1], 16;" :: "r"(dst), "l"(src))
#define CP_COMMIT() asm volatile("cp.async.commit_group;")
#define CP_WAIT1()  asm volatile("cp.async.wait_group 1;")
#define CP_WAIT0()  asm volatile("cp.async.wait_group 0;")

#define LDSM4(r0, r1, r2, r3, addr) \
    asm volatile("ldmatrix.sync.aligned.m8n8.x4.shared.b16 {%0,%1,%2,%3}, [%4];" \
        : "=r"(r0), "=r"(r1), "=r"(r2), "=r"(r3) : "r"(addr))

#define MMA16816(d, a, b0, b1) \
    asm volatile("mma.sync.aligned.m16n8k16.row.col.f32.bf16.bf16.f32 " \
        "{%0,%1,%2,%3}, {%4,%5,%6,%7}, {%8,%9}, {%0,%1,%2,%3};" \
        : "+f"(d[0]), "+f"(d[1]), "+f"(d[2]), "+f"(d[3]) \
        : "r"(a[0]), "r"(a[1]), "r"(a[2]), "r"(a[3]), "r"(b0), "r"(b1))

__device__ __forceinline__ void split_bf16(float v, __nv_bfloat16& h, __nv_bfloat16& l) {
    h = __float2bfloat16_rn(v);
    l = __float2bfloat16_rn(v - __bfloat162float(h));
}

// ---------------- setup / split kernels ----------------
__global__ void k_setup(const float* __restrict__ nu_log,
                        const float* __restrict__ theta_log) {
    int n = blockIdx.x * blockDim.x + threadIdx.x;
    if (n >= N_ST) return;
    float lm = expf(-expf(nu_log[n]));
    float th = expf(theta_log[n]);
    float2 lam = make_float2(lm * cosf(th), lm * sinf(th));
    g_lam[n] = lam;
    float2 p = lam;
#pragma unroll
    for (int i = 0; i < 7; i++) {
        float2 q;
        q.x = p.x * p.x - p.y * p.y;
        q.y = 2.0f * p.x * p.y;
        p = q;
    }
    g_lamL[n] = p;
}

__global__ void k_splitB(const float* __restrict__ gamma_log,
                         const float* __restrict__ Br,
                         const float* __restrict__ Bi) {
    int idx = blockIdx.x * blockDim.x + threadIdx.x;
    if (idx >= NBU * D_INP) return;
    int nn = idx / D_INP, i = idx % D_INP;
    int n = (nn < N_ST) ? nn : nn - N_ST;
    float g = expf(gamma_log[n]);
    float v = g * ((nn < N_ST) ? Br[n * D_INP + i] : Bi[n * D_INP + i]);
    split_bf16(v, g_B1h[idx], g_B1l[idx]);
}

__global__ void k_buildW2(const float* __restrict__ Cr,
                          const float* __restrict__ Ci,
                          const float* __restrict__ Dm) {
    int idx = blockIdx.x * blockDim.x + threadIdx.x;
    if (idx >= D_OUTP * KCAT) return;
    int o = idx / KCAT, k = idx % KCAT;
    float v;
    if (k < N_ST)     v =  2.0f * Cr[o * N_ST + k];
    else if (k < NBU) v = -2.0f * Ci[o * N_ST + (k - N_ST)];
    else              v =         Dm[o * D_INP + (k - NBU)];
    split_bf16(v, g_W2h[idx], g_W2l[idx]);
}

__global__ void k_splitU(const float* __restrict__ u) {
    int idx = blockIdx.x * blockDim.x + threadIdx.x;
    if (idx >= M_TOT * D_INP) return;
    int m = idx / D_INP, i = idx % D_INP;
    __nv_bfloat16 h, l;
    split_bf16(u[idx], h, l);
    size_t off = (size_t)m * KCAT + NBU + i;
    g_A2h[off] = h;
    g_A2l[off] = l;
}

// ---------------- bf16-split HMMA GEMM ----------------
// C[M,N] = (Ah+Al)[m,k] * (Bh+Bl)[n,k]^T, dropping Al*Bl.
// CTA tile 128x128, BK=32, 8 warps (2x4), warp tile 64x32, mma.m16n8k16.
#define BK       32
#define PADK     40                      // padded k-stride (elems)
#define TILE_B   (128 * PADK * 2)        // 10240 B per tile
#define STAGES   3
#define SMEM_GEMM (STAGES * 4 * TILE_B)  // 122880 B

__global__ __launch_bounds__(256, 1)
void gemm_split_mma(const __nv_bfloat16* __restrict__ Ah,
                    const __nv_bfloat16* __restrict__ Al,
                    const __nv_bfloat16* __restrict__ Bh,
                    const __nv_bfloat16* __restrict__ Bl,
                    float* __restrict__ C,
                    int K, int lda, int ldb, int ldc) {
    extern __shared__ char smem[];
    const uint32_t sb = smem_u32(smem);
    const int tid = threadIdx.x;
    const int wid = tid >> 5, lid = tid & 31;
    const int m0 = blockIdx.y * 128;
    const int n0 = blockIdx.x * 128;
    const int NC = K / BK;

    const int wm = wid >> 2;             // 0..1
    const int wn = wid & 3;              // 0..3

    // loader: 4 tiles [Ah, Al, Bh, Bl] x 128 rows x 64B, 16B per cp.async
    const int l_tile = tid >> 6;                 // 0..3 (64 threads per tile)
    const int l_row0 = (tid >> 2) & 15;          // 0..15 (x8 iters -> 128 rows)
    const int l_c8   = tid & 3;                  // 16B chunk in row

    auto issue_load = [&](int c) {
        const int s = c % STAGES;
        const uint32_t stb = sb + s * 4 * TILE_B + l_tile * TILE_B;
        const int k0 = c * BK + l_c8 * 8;
        const __nv_bfloat16* gsrc;
        int ld;
        if (l_tile == 0)      { gsrc = Ah + (size_t)m0 * lda; ld = lda; }
        else if (l_tile == 1) { gsrc = Al + (size_t)m0 * lda; ld = lda; }
        else if (l_tile == 2) { gsrc = Bh + (size_t)n0 * ldb; ld = ldb; }
        else                  { gsrc = Bl + (size_t)n0 * ldb; ld = ldb; }
#pragma unroll
        for (int it = 0; it < 8; it++) {
            const int row = l_row0 + it * 16;
            CP_ASYNC16(stb + (uint32_t)(row * (PADK * 2) + l_c8 * 16),
                       gsrc + (size_t)row * ld + k0);
        }
        CP_COMMIT();
    };

    float acc[4][4][4];
#pragma unroll
    for (int i = 0; i < 4; i++)
#pragma unroll
        for (int j = 0; j < 4; j++)
#pragma unroll
            for (int q = 0; q < 4; q++) acc[i][j][q] = 0.0f;

    // ldmatrix lane addressing
    const int aRow = lid & 15;                   // row within m16
    const int aCol = (lid >> 4) << 3;            // 0 or 8 (k)
    const int bRow = (lid & 7) + ((lid >> 4) << 3);  // n row within n16
    const int bCol = ((lid >> 3) & 1) << 3;          // 0 or 8 (k)

    issue_load(0);
    issue_load(1);

    for (int c = 0; c < NC; c++) {
        CP_WAIT1();
        __syncthreads();
        if (c + 2 < NC) issue_load(c + 2);

        const uint32_t stb = sb + (c % STAGES) * 4 * TILE_B;
        const uint32_t sAh = stb;
        const uint32_t sAl = stb + TILE_B;
        const uint32_t sBh = stb + 2 * TILE_B;
        const uint32_t sBl = stb + 3 * TILE_B;

#pragma unroll
        for (int kk = 0; kk < BK; kk += 16) {
            uint32_t ah[4][4], al[4][4], bh[2][4], bl[2][4];
#pragma unroll
            for (int mf = 0; mf < 4; mf++) {
                uint32_t ad = sAh + (uint32_t)((wm * 64 + mf * 16 + aRow) * (PADK * 2) + (kk + aCol) * 2);
                LDSM4(ah[mf][0], ah[mf][1], ah[mf][2], ah[mf][3], ad);
            }
#pragma unroll
            for (int p = 0; p < 2; p++) {
                uint32_t bd = sBh + (uint32_t)((wn * 32 + p * 16 + bRow) * (PADK * 2) + (kk + bCol) * 2);
                LDSM4(bh[p][0], bh[p][1], bh[p][2], bh[p][3], bd);
            }
            // pass hh
#pragma unroll
            for (int mf = 0; mf < 4; mf++)
#pragma unroll
                for (int nf = 0; nf < 4; nf++)
                    MMA16816(acc[mf][nf], ah[mf], bh[nf >> 1][(nf & 1) * 2], bh[nf >> 1][(nf & 1) * 2 + 1]);
            // pass lh: Al x Bh
#pragma unroll
            for (int mf = 0; mf < 4; mf++) {
                uint32_t ad = sAl + (uint32_t)((wm * 64 + mf * 16 + aRow) * (PADK * 2) + (kk + aCol) * 2);
                LDSM4(al[mf][0], al[mf][1], al[mf][2], al[mf][3], ad);
            }
#pragma unroll
            for (int mf = 0; mf < 4; mf++)
#pragma unroll
                for (int nf = 0; nf < 4; nf++)
                    MMA16816(acc[mf][nf], al[mf], bh[nf >> 1][(nf & 1) * 2], bh[nf >> 1][(nf & 1) * 2 + 1]);
            // pass hl: Ah x Bl
#pragma unroll
            for (int p = 0; p < 2; p++) {
                uint32_t bd = sBl + (uint32_t)((wn * 32 + p * 16 + bRow) * (PADK * 2) + (kk + bCol) * 2);
                LDSM4(bl[p][0], bl[p][1], bl[p][2], bl[p][3], bd);
            }
#pragma unroll
            for (int mf = 0; mf < 4; mf++)
#pragma unroll
                for (int nf = 0; nf < 4; nf++)
                    MMA16816(acc[mf][nf], ah[mf], bl[nf >> 1][(nf & 1) * 2], bl[nf >> 1][(nf & 1) * 2 + 1]);
        }
        __syncthreads();
    }
    CP_WAIT0();

    // epilogue
    const int gid = lid >> 2, tig = lid & 3;
#pragma unroll
    for (int mf = 0; mf < 4; mf++) {
        const int row = m0 + wm * 64 + mf * 16 + gid;
#pragma unroll
        for (int nf = 0; nf < 4; nf++) {
            const int col = n0 + wn * 32 + nf * 8 + tig * 2;
            *(float2*)(C + (size_t)row * ldc + col) =
                make_float2(acc[mf][nf][0], acc[mf][nf][1]);
            *(float2*)(C + (size_t)(row + 8) * ldc + col) =
                make_float2(acc[mf][nf][2], acc[mf][nf][3]);
        }
    }
}

// ---------------- chunked complex scan ----------------
__global__ void k_scan_final() {
    int id = blockIdx.x * blockDim.x + threadIdx.x;
    if (id >= B_SZ * NCHUNK * N_ST) return;
    int n = id & (N_ST - 1);
    int c = (id >> 9) & (NCHUNK - 1);
    int b = id >> 14;
    float2 lam = g_lam[n];
    float xr = 0.0f, xi = 0.0f;
    const float* base = g_Bu + ((size_t)(b * T_LEN + c * CHUNK)) * NBU + n;
#pragma unroll 4
    for (int t = 0; t < CHUNK; t++) {
        float br = base[(size_t)t * NBU];
        float bi = base[(size_t)t * NBU + N_ST];
        float nxr = fmaf(lam.x, xr, fmaf(-lam.y, xi, br));
        float nxi = fmaf(lam.x, xi, fmaf(lam.y, xr, bi));
        xr = nxr; xi = nxi;
    }
    g_F[id] = make_float2(xr, xi);
}

__global__ void k_chunk_prefix() {
    int id = blockIdx.x * blockDim.x + threadIdx.x;
    if (id >= B_SZ * N_ST) return;
    int n = id & (N_ST - 1);
    int b = id >> 9;
    float2 lamL = g_lamL[n];
    float sr = 0.0f, si = 0.0f;
#pragma unroll
    for (int c = 0; c < NCHUNK; c++) {
        int idx = (b * NCHUNK + c) * N_ST + n;
        g_carry[idx] = make_float2(sr, si);
        float2 f = g_F[idx];
        float nsr = fmaf(lamL.x, sr, fmaf(-lamL.y, si, f.x));
        float nsi = fmaf(lamL.x, si, fmaf(lamL.y, sr, f.y));
        sr = nsr; si = nsi;
    }
}

__global__ void k_scan_write() {
    int id = blockIdx.x * blockDim.x + threadIdx.x;
    if (id >= B_SZ * NCHUNK * N_ST) return;
    int n = id & (N_ST - 1);
    int c = (id >> 9) & (NCHUNK - 1);
    int b = id >> 14;
    float2 lam = g_lam[n];
    float2 cin = g_carry[id];
    float xr = cin.x, xi = cin.y;
    const float* base = g_Bu + ((size_t)(b * T_LEN + c * CHUNK)) * NBU + n;
    __nv_bfloat16* xh = g_A2h + ((size_t)(b * T_LEN + c * CHUNK)) * KCAT + n;
    __nv_bfloat16* xl = g_A2l + ((size_t)(b * T_LEN + c * CHUNK)) * KCAT + n;
#pragma unroll 4
    for (int t = 0; t < CHUNK; t++) {
        float br = base[(size_t)t * NBU];
        float bi = base[(size_t)t * NBU + N_ST];
        float nxr = fmaf(lam.x, xr, fmaf(-lam.y, xi, br));
        float nxi = fmaf(lam.x, xi, fmaf(lam.y, xr, bi));
        xr = nxr; xi = nxi;
        __nv_bfloat16 h, l;
        split_bf16(xr, h, l);
        xh[(size_t)t * KCAT] = h;
        xl[(size_t)t * KCAT] = l;
        split_bf16(xi, h, l);
        xh[(size_t)t * KCAT + N_ST] = h;
        xl[(size_t)t * KCAT + N_ST] = l;
    }
}

// ---------------- launch ----------------
extern "C" void kernel_launch(void* const* d_in, const int* in_sizes, int n_in,
                              void* d_out, int out_size) {
    const float* u_in      = (const float*)d_in[0];
    const float* nu_log    = (const float*)d_in[1];
    const float* theta_log = (const float*)d_in[2];
    const float* gamma_log = (const float*)d_in[3];
    const float* B_real    = (const float*)d_in[4];
    const float* B_imag    = (const float*)d_in[5];
    const float* C_real    = (const float*)d_in[6];
    const float* C_imag    = (const float*)d_in[7];
    const float* Dm        = (const float*)d_in[8];
    float* y = (float*)d_out;

    __nv_bfloat16 *a2h, *a2l, *b1h, *b1l, *w2h, *w2l;
    float* bu;
    cudaGetSymbolAddress((void**)&a2h, g_A2h);
    cudaGetSymbolAddress((void**)&a2l, g_A2l);
    cudaGetSymbolAddress((void**)&b1h, g_B1h);
    cudaGetSymbolAddress((void**)&b1l, g_B1l);
    cudaGetSymbolAddress((void**)&w2h, g_W2h);
    cudaGetSymbolAddress((void**)&w2l, g_W2l);
    cudaGetSymbolAddress((void**)&bu,  g_Bu);

    cudaFuncSetAttribute(gemm_split_mma,
                         cudaFuncAttributeMaxDynamicSharedMemorySize, SMEM_GEMM);

    // setup / splits
    k_setup<<<2, 256>>>(nu_log, theta_log);
    k_splitB<<<(NBU * D_INP + 255) / 256, 256>>>(gamma_log, B_real, B_imag);
    k_buildW2<<<(D_OUTP * KCAT + 255) / 256, 256>>>(C_real, C_imag, Dm);
    k_splitU<<<(M_TOT * D_INP + 255) / 256, 256>>>(u_in);

    // GEMM 1: Bu[M, 1024] = u @ (gamma*B)^T   (A = u columns of A2, lda=KCAT)
    {
        dim3 grid(NBU / 128, M_TOT / 128);
        gemm_split_mma<<<grid, 256, SMEM_GEMM>>>(a2h + NBU, a2l + NBU, b1h, b1l,
                                                 bu, D_INP, KCAT, D_INP, NBU);
    }

    // scan: Bu -> X (bf16 hi/lo into A2 cols 0..1023)
    k_scan_final<<<(B_SZ * NCHUNK * N_ST + 255) / 256, 256>>>();
    k_chunk_prefix<<<(B_SZ * N_ST + 255) / 256, 256>>>();
    k_scan_write<<<(B_SZ * NCHUNK * N_ST + 255) / 256, 256>>>();

    // GEMM 2 (+3 fused): y[M, 256] = [X | u] @ [2Cr | -2Ci | D]^T, K=1280
    {
        dim3 grid(D_OUTP / 128, M_TOT / 128);
        gemm_split_mma<<<grid, 256, SMEM_GEMM>>>(a2h, a2l, w2h, w2l,
                                                 y, KCAT, KCAT, KCAT, D_OUTP);
    }
}

// round 4
// speedup vs baseline: 2.2267x; 1.3525x over previous
#include <cuda_runtime.h>
#include <cuda_fp16.h>
#include <cstdint>

// ---------------- problem constants ----------------
#define B_SZ   8
#define T_LEN  4096
#define D_INP  256
#define D_OUTP 256
#define N_ST   512
#define M_TOT  (B_SZ * T_LEN)      // 32768
#define NBU    (2 * N_ST)          // 1024
#define KCAT   (NBU + D_INP)       // 1280
#define CHUNK  128
#define NCHUNK (T_LEN / CHUNK)     // 32

// ---------------- device scratch ----------------
__device__ __half g_A2[(size_t)M_TOT * KCAT];    // fp16 [X | u]
__device__ float  g_Bu[(size_t)M_TOT * NBU];     // fp32 driving term
__device__ __half g_B1h[NBU * D_INP];            // gamma-scaled B, hi
__device__ __half g_B1l[NBU * D_INP];            // lo residual
__device__ __half g_W2h[D_OUTP * KCAT];          // [2Cr | -2Ci | D], hi
__device__ __half g_W2l[D_OUTP * KCAT];
__device__ float2 g_lam [N_ST];
__device__ float2 g_lamL[N_ST];
__device__ float2 g_F    [B_SZ * NCHUNK * N_ST];
__device__ float2 g_carry[B_SZ * NCHUNK * N_ST];

// ---------------- helpers ----------------
__device__ __forceinline__ uint32_t smem_u32(const void* p) {
    uint32_t a;
    asm("{ .reg .u64 t; cvta.to.shared.u64 t, %1; cvt.u32.u64 %0, t; }" : "=r"(a) : "l"(p));
    return a;
}

#define CP_ASYNC16(dst, src) \
    asm volatile("cp.async.cg.shared.global [%0], [%1], 16;" :: "r"(dst), "l"(src))
#define CP_COMMIT() asm volatile("cp.async.commit_group;")
#define CP_WAIT2()  asm volatile("cp.async.wait_group 2;")
#define CP_WAIT0()  asm volatile("cp.async.wait_group 0;")

#define LDSM4(r0, r1, r2, r3, addr) \
    asm volatile("ldmatrix.sync.aligned.m8n8.x4.shared.b16 {%0,%1,%2,%3}, [%4];" \
        : "=r"(r0), "=r"(r1), "=r"(r2), "=r"(r3) : "r"(addr))

#define MMA16816(d, a, b0, b1) \
    asm volatile("mma.sync.aligned.m16n8k16.row.col.f32.f16.f16.f32 " \
        "{%0,%1,%2,%3}, {%4,%5,%6,%7}, {%8,%9}, {%0,%1,%2,%3};" \
        : "+f"(d[0]), "+f"(d[1]), "+f"(d[2]), "+f"(d[3]) \
        : "r"(a[0]), "r"(a[1]), "r"(a[2]), "r"(a[3]), "r"(b0), "r"(b1))

__device__ __forceinline__ void split_h(float v, __half& h, __half& l) {
    h = __float2half_rn(v);
    l = __float2half_rn(v - __half2float(h));
}

// ---------------- setup / split kernels ----------------
__global__ void k_setup(const float* __restrict__ nu_log,
                        const float* __restrict__ theta_log) {
    int n = blockIdx.x * blockDim.x + threadIdx.x;
    if (n >= N_ST) return;
    float lm = expf(-expf(nu_log[n]));
    float th = expf(theta_log[n]);
    float2 lam = make_float2(lm * cosf(th), lm * sinf(th));
    g_lam[n] = lam;
    float2 p = lam;
#pragma unroll
    for (int i = 0; i < 7; i++) {
        float2 q;
        q.x = p.x * p.x - p.y * p.y;
        q.y = 2.0f * p.x * p.y;
        p = q;
    }
    g_lamL[n] = p;
}

__global__ void k_splitB(const float* __restrict__ gamma_log,
                         const float* __restrict__ Br,
                         const float* __restrict__ Bi) {
    int idx = blockIdx.x * blockDim.x + threadIdx.x;
    if (idx >= NBU * D_INP) return;
    int nn = idx / D_INP, i = idx % D_INP;
    int n = (nn < N_ST) ? nn : nn - N_ST;
    float g = expf(gamma_log[n]);
    float v = g * ((nn < N_ST) ? Br[n * D_INP + i] : Bi[n * D_INP + i]);
    split_h(v, g_B1h[idx], g_B1l[idx]);
}

__global__ void k_buildW2(const float* __restrict__ Cr,
                          const float* __restrict__ Ci,
                          const float* __restrict__ Dm) {
    int idx = blockIdx.x * blockDim.x + threadIdx.x;
    if (idx >= D_OUTP * KCAT) return;
    int o = idx / KCAT, k = idx % KCAT;
    float v;
    if (k < N_ST)     v =  2.0f * Cr[o * N_ST + k];
    else if (k < NBU) v = -2.0f * Ci[o * N_ST + (k - N_ST)];
    else              v =         Dm[o * D_INP + (k - NBU)];
    split_h(v, g_W2h[idx], g_W2l[idx]);
}

__global__ void k_cvtU(const float* __restrict__ u) {
    int idx = blockIdx.x * blockDim.x + threadIdx.x;
    if (idx >= M_TOT * D_INP / 2) return;
    int m = idx / (D_INP / 2), i = (idx % (D_INP / 2)) * 2;
    float2 v = *(const float2*)(u + (size_t)m * D_INP + i);
    __half2 h = __floats2half2_rn(v.x, v.y);
    *(__half2*)(g_A2 + (size_t)m * KCAT + NBU + i) = h;
}

// ---------------- fp16 weight-split HMMA GEMM ----------------
// C[M,N] = A[m,k] * (Bh+Bl)[n,k]^T ; A fp16, weights split hi/lo.
// CTA tile 128x128, BK=32, 8 warps (2x4), warp tile 64x32, mma.m16n8k16.
#define BK       32
#define PADK     40                       // padded k-stride (elems)
#define TILE_B   (128 * PADK * 2)         // 10240 B per tile
#define STAGES   4
#define SMEM_GEMM (STAGES * 3 * TILE_B)   // 122880 B

__global__ __launch_bounds__(256, 1)
void gemm_wsplit_mma(const __half* __restrict__ A,
                     const __half* __restrict__ Bh,
                     const __half* __restrict__ Bl,
                     float* __restrict__ C,
                     int K, int lda, int ldb, int ldc) {
    extern __shared__ char smem[];
    const uint32_t sb = smem_u32(smem);
    const int tid = threadIdx.x;
    const int wid = tid >> 5, lid = tid & 31;
    const int m0 = blockIdx.y * 128;
    const int n0 = blockIdx.x * 128;
    const int NC = K / BK;

    const int wm = wid >> 2;             // 0..1
    const int wn = wid & 3;              // 0..3

    const __half* A0  = A  + (size_t)m0 * lda;
    const __half* Bh0 = Bh + (size_t)n0 * ldb;
    const __half* Bl0 = Bl + (size_t)n0 * ldb;

    // loader: 3 tiles x (128 rows x 64B) ; 512 x 16B per tile; 256 threads.
    auto issue_load = [&](int c) {
        const int s = c % STAGES;
        const uint32_t stb = sb + s * 3 * TILE_B;
        const int k0 = c * BK;
#pragma unroll
        for (int r = 0; r < 2; r++) {
            int idx = tid + r * 256;                 // 0..511
            int row = idx >> 2, ch = idx & 3;
            uint32_t soff = (uint32_t)(row * (PADK * 2) + ch * 16);
            size_t goff = (size_t)row * lda + k0 + ch * 8;
            CP_ASYNC16(stb + soff, A0 + goff);
        }
#pragma unroll
        for (int r = 0; r < 2; r++) {
            int idx = tid + r * 256;
            int row = idx >> 2, ch = idx & 3;
            uint32_t soff = (uint32_t)(row * (PADK * 2) + ch * 16);
            size_t goff = (size_t)row * ldb + k0 + ch * 8;
            CP_ASYNC16(stb + TILE_B + soff, Bh0 + goff);
            CP_ASYNC16(stb + 2 * TILE_B + soff, Bl0 + goff);
        }
        CP_COMMIT();
    };

    float acc[4][4][4];
#pragma unroll
    for (int i = 0; i < 4; i++)
#pragma unroll
        for (int j = 0; j < 4; j++)
#pragma unroll
            for (int q = 0; q < 4; q++) acc[i][j][q] = 0.0f;

    // ldmatrix lane addressing
    const int aRow = lid & 15;
    const int aCol = (lid >> 4) << 3;
    const int bRow = (lid & 7) + ((lid >> 4) << 3);
    const int bCol = ((lid >> 3) & 1) << 3;

    issue_load(0);
    issue_load(1);
    issue_load(2);

    for (int c = 0; c < NC; c++) {
        CP_WAIT2();
        __syncthreads();
        if (c + 3 < NC) issue_load(c + 3);
        else            CP_COMMIT();       // keep group count invariant

        const uint32_t stb = sb + (c % STAGES) * 3 * TILE_B;
        const uint32_t sA  = stb;
        const uint32_t sBh = stb + TILE_B;
        const uint32_t sBl = stb + 2 * TILE_B;

#pragma unroll
        for (int kk = 0; kk < BK; kk += 16) {
            uint32_t a[4][4], bh[2][4], bl[2][4];
#pragma unroll
            for (int mf = 0; mf < 4; mf++) {
                uint32_t ad = sA + (uint32_t)((wm * 64 + mf * 16 + aRow) * (PADK * 2) + (kk + aCol) * 2);
                LDSM4(a[mf][0], a[mf][1], a[mf][2], a[mf][3], ad);
            }
#pragma unroll
            for (int p = 0; p < 2; p++) {
                uint32_t bd = sBh + (uint32_t)((wn * 32 + p * 16 + bRow) * (PADK * 2) + (kk + bCol) * 2);
                LDSM4(bh[p][0], bh[p][1], bh[p][2], bh[p][3], bd);
            }
#pragma unroll
            for (int p = 0; p < 2; p++) {
                uint32_t bd = sBl + (uint32_t)((wn * 32 + p * 16 + bRow) * (PADK * 2) + (kk + bCol) * 2);
                LDSM4(bl[p][0], bl[p][1], bl[p][2], bl[p][3], bd);
            }
            // pass 1: A x Bh
#pragma unroll
            for (int mf = 0; mf < 4; mf++)
#pragma unroll
                for (int nf = 0; nf < 4; nf++)
                    MMA16816(acc[mf][nf], a[mf], bh[nf >> 1][(nf & 1) * 2], bh[nf >> 1][(nf & 1) * 2 + 1]);
            // pass 2: A x Bl
#pragma unroll
            for (int mf = 0; mf < 4; mf++)
#pragma unroll
                for (int nf = 0; nf < 4; nf++)
                    MMA16816(acc[mf][nf], a[mf], bl[nf >> 1][(nf & 1) * 2], bl[nf >> 1][(nf & 1) * 2 + 1]);
        }
        __syncthreads();
    }
    CP_WAIT0();

    // epilogue
    const int gid = lid >> 2, tig = lid & 3;
#pragma unroll
    for (int mf = 0; mf < 4; mf++) {
        const int row = m0 + wm * 64 + mf * 16 + gid;
#pragma unroll
        for (int nf = 0; nf < 4; nf++) {
            const int col = n0 + wn * 32 + nf * 8 + tig * 2;
            *(float2*)(C + (size_t)row * ldc + col) =
                make_float2(acc[mf][nf][0], acc[mf][nf][1]);
            *(float2*)(C + (size_t)(row + 8) * ldc + col) =
                make_float2(acc[mf][nf][2], acc[mf][nf][3]);
        }
    }
}

// ---------------- chunked complex scan ----------------
__global__ void k_scan_final() {
    int id = blockIdx.x * blockDim.x + threadIdx.x;
    if (id >= B_SZ * NCHUNK * N_ST) return;
    int n = id & (N_ST - 1);
    int c = (id >> 9) & (NCHUNK - 1);
    int b = id >> 14;
    float2 lam = g_lam[n];
    float xr = 0.0f, xi = 0.0f;
    const float* base = g_Bu + ((size_t)(b * T_LEN + c * CHUNK)) * NBU + n;
#pragma unroll 4
    for (int t = 0; t < CHUNK; t++) {
        float br = base[(size_t)t * NBU];
        float bi = base[(size_t)t * NBU + N_ST];
        float nxr = fmaf(lam.x, xr, fmaf(-lam.y, xi, br));
        float nxi = fmaf(lam.x, xi, fmaf(lam.y, xr, bi));
        xr = nxr; xi = nxi;
    }
    g_F[id] = make_float2(xr, xi);
}

__global__ void k_chunk_prefix() {
    int id = blockIdx.x * blockDim.x + threadIdx.x;
    if (id >= B_SZ * N_ST) return;
    int n = id & (N_ST - 1);
    int b = id >> 9;
    float2 lamL = g_lamL[n];
    float sr = 0.0f, si = 0.0f;
#pragma unroll
    for (int c = 0; c < NCHUNK; c++) {
        int idx = (b * NCHUNK + c) * N_ST + n;
        g_carry[idx] = make_float2(sr, si);
        float2 f = g_F[idx];
        float nsr = fmaf(lamL.x, sr, fmaf(-lamL.y, si, f.x));
        float nsi = fmaf(lamL.x, si, fmaf(lamL.y, sr, f.y));
        sr = nsr; si = nsi;
    }
}

__global__ void k_scan_write() {
    int id = blockIdx.x * blockDim.x + threadIdx.x;
    if (id >= B_SZ * NCHUNK * N_ST) return;
    int n = id & (N_ST - 1);
    int c = (id >> 9) & (NCHUNK - 1);
    int b = id >> 14;
    float2 lam = g_lam[n];
    float2 cin = g_carry[id];
    float xr = cin.x, xi = cin.y;
    const float* base = g_Bu + ((size_t)(b * T_LEN + c * CHUNK)) * NBU + n;
    __half* xo = g_A2 + ((size_t)(b * T_LEN + c * CHUNK)) * KCAT + n;
#pragma unroll 4
    for (int t = 0; t < CHUNK; t++) {
        float br = base[(size_t)t * NBU];
        float bi = base[(size_t)t * NBU + N_ST];
        float nxr = fmaf(lam.x, xr, fmaf(-lam.y, xi, br));
        float nxi = fmaf(lam.x, xi, fmaf(lam.y, xr, bi));
        xr = nxr; xi = nxi;
        xo[(size_t)t * KCAT]        = __float2half_rn(xr);
        xo[(size_t)t * KCAT + N_ST] = __float2half_rn(xi);
    }
}

// ---------------- launch ----------------
extern "C" void kernel_launch(void* const* d_in, const int* in_sizes, int n_in,
                              void* d_out, int out_size) {
    const float* u_in      = (const float*)d_in[0];
    const float* nu_log    = (const float*)d_in[1];
    const float* theta_log = (const float*)d_in[2];
    const float* gamma_log = (const float*)d_in[3];
    const float* B_real    = (const float*)d_in[4];
    const float* B_imag    = (const float*)d_in[5];
    const float* C_real    = (const float*)d_in[6];
    const float* C_imag    = (const float*)d_in[7];
    const float* Dm        = (const float*)d_in[8];
    float* y = (float*)d_out;

    __half *a2, *b1h, *b1l, *w2h, *w2l;
    float* bu;
    cudaGetSymbolAddress((void**)&a2,  g_A2);
    cudaGetSymbolAddress((void**)&b1h, g_B1h);
    cudaGetSymbolAddress((void**)&b1l, g_B1l);
    cudaGetSymbolAddress((void**)&w2h, g_W2h);
    cudaGetSymbolAddress((void**)&w2l, g_W2l);
    cudaGetSymbolAddress((void**)&bu,  g_Bu);

    cudaFuncSetAttribute(gemm_wsplit_mma,
                         cudaFuncAttributeMaxDynamicSharedMemorySize, SMEM_GEMM);

    // setup / splits
    k_setup<<<2, 256>>>(nu_log, theta_log);
    k_splitB<<<(NBU * D_INP + 255) / 256, 256>>>(gamma_log, B_real, B_imag);
    k_buildW2<<<(D_OUTP * KCAT + 255) / 256, 256>>>(C_real, C_imag, Dm);
    k_cvtU<<<(M_TOT * D_INP / 2 + 255) / 256, 256>>>(u_in);

    // GEMM 1: Bu[M, 1024] = u @ (gamma*B)^T  (A = u columns of A2, lda=KCAT)
    {
        dim3 grid(NBU / 128, M_TOT / 128);
        gemm_wsplit_mma<<<grid, 256, SMEM_GEMM>>>(a2 + NBU, b1h, b1l,
                                                  bu, D_INP, KCAT, D_INP, NBU);
    }

    // scan: Bu -> X (fp16 into A2 cols 0..1023)
    k_scan_final<<<(B_SZ * NCHUNK * N_ST + 255) / 256, 256>>>();
    k_chunk_prefix<<<(B_SZ * N_ST + 255) / 256, 256>>>();
    k_scan_write<<<(B_SZ * NCHUNK * N_ST + 255) / 256, 256>>>();

    // GEMM 2 (+3 fused): y[M, 256] = [X | u] @ [2Cr | -2Ci | D]^T, K=1280
    {
        dim3 grid(D_OUTP / 128, M_TOT / 128);
        gemm_wsplit_mma<<<grid, 256, SMEM_GEMM>>>(a2, w2h, w2l,
                                                  y, KCAT, KCAT, KCAT, D_OUTP);
    }
}

// round 5
// speedup vs baseline: 2.6485x; 1.1894x over previous
#include <cuda_runtime.h>
#include <cuda_fp16.h>
#include <cstdint>

// ---------------- problem constants ----------------
#define B_SZ   8
#define T_LEN  4096
#define D_INP  256
#define D_OUTP 256
#define N_ST   512
#define M_TOT  (B_SZ * T_LEN)      // 32768
#define NBU    (2 * N_ST)          // 1024
#define KCAT   (NBU + D_INP)       // 1280
#define CHUNK  128
#define NCHUNK (T_LEN / CHUNK)     // 32

// ---------------- device scratch ----------------
// A2 layout: cols [0,1024) = X interleaved (2n = xr_n, 2n+1 = xi_n), cols [1024,1280) = u
__device__ __half g_A2[(size_t)M_TOT * KCAT];
__device__ __half g_B1h[NBU * D_INP];            // gamma-scaled B, interleaved rows, hi
__device__ __half g_B1l[NBU * D_INP];
__device__ __half g_W2h[D_OUTP * KCAT];          // K-interleaved [2Cr/-2Ci | D], hi
__device__ __half g_W2l[D_OUTP * KCAT];
__device__ float2 g_lam [N_ST];
__device__ float2 g_lamL[N_ST];
__device__ float2 g_F    [B_SZ * NCHUNK * N_ST];
__device__ float2 g_carry[B_SZ * NCHUNK * N_ST];

// ---------------- helpers ----------------
__device__ __forceinline__ uint32_t smem_u32(const void* p) {
    uint32_t a;
    asm("{ .reg .u64 t; cvta.to.shared.u64 t, %1; cvt.u32.u64 %0, t; }" : "=r"(a) : "l"(p));
    return a;
}

#define CP_ASYNC16(dst, src) \
    asm volatile("cp.async.cg.shared.global [%0], [%1], 16;" :: "r"(dst), "l"(src))
#define CP_COMMIT() asm volatile("cp.async.commit_group;")
#define CP_WAIT2()  asm volatile("cp.async.wait_group 2;")
#define CP_WAIT0()  asm volatile("cp.async.wait_group 0;")

#define LDSM4(r0, r1, r2, r3, addr) \
    asm volatile("ldmatrix.sync.aligned.m8n8.x4.shared.b16 {%0,%1,%2,%3}, [%4];" \
        : "=r"(r0), "=r"(r1), "=r"(r2), "=r"(r3) : "r"(addr))

#define MMA16816(d, a, b0, b1) \
    asm volatile("mma.sync.aligned.m16n8k16.row.col.f32.f16.f16.f32 " \
        "{%0,%1,%2,%3}, {%4,%5,%6,%7}, {%8,%9}, {%0,%1,%2,%3};" \
        : "+f"(d[0]), "+f"(d[1]), "+f"(d[2]), "+f"(d[3]) \
        : "r"(a[0]), "r"(a[1]), "r"(a[2]), "r"(a[3]), "r"(b0), "r"(b1))

__device__ __forceinline__ void split_h(float v, __half& h, __half& l) {
    h = __float2half_rn(v);
    l = __float2half_rn(v - __half2float(h));
}

// ---------------- setup / split kernels ----------------
__global__ void k_setup(const float* __restrict__ nu_log,
                        const float* __restrict__ theta_log) {
    int n = blockIdx.x * blockDim.x + threadIdx.x;
    if (n >= N_ST) return;
    float lm = expf(-expf(nu_log[n]));
    float th = expf(theta_log[n]);
    float2 lam = make_float2(lm * cosf(th), lm * sinf(th));
    g_lam[n] = lam;
    float2 p = lam;
#pragma unroll
    for (int i = 0; i < 7; i++) {
        float2 q;
        q.x = p.x * p.x - p.y * p.y;
        q.y = 2.0f * p.x * p.y;
        p = q;
    }
    g_lamL[n] = p;
}

// interleaved rows: row 2n = gamma*Br[n], row 2n+1 = gamma*Bi[n]
__global__ void k_splitB(const float* __restrict__ gamma_log,
                         const float* __restrict__ Br,
                         const float* __restrict__ Bi) {
    int idx = blockIdx.x * blockDim.x + threadIdx.x;
    if (idx >= NBU * D_INP) return;
    int nn = idx / D_INP, i = idx % D_INP;
    int n = nn >> 1;
    float g = expf(gamma_log[n]);
    float v = g * (((nn & 1) == 0) ? Br[n * D_INP + i] : Bi[n * D_INP + i]);
    split_h(v, g_B1h[idx], g_B1l[idx]);
}

// K-interleaved weights: k=2n -> 2Cr[o][n], k=2n+1 -> -2Ci[o][n], k>=1024 -> D
__global__ void k_buildW2(const float* __restrict__ Cr,
                          const float* __restrict__ Ci,
                          const float* __restrict__ Dm) {
    int idx = blockIdx.x * blockDim.x + threadIdx.x;
    if (idx >= D_OUTP * KCAT) return;
    int o = idx / KCAT, k = idx % KCAT;
    float v;
    if (k < NBU) {
        int n = k >> 1;
        v = ((k & 1) == 0) ? 2.0f * Cr[o * N_ST + n] : -2.0f * Ci[o * N_ST + n];
    } else {
        v = Dm[o * D_INP + (k - NBU)];
    }
    split_h(v, g_W2h[idx], g_W2l[idx]);
}

__global__ void k_cvtU(const float* __restrict__ u) {
    int idx = blockIdx.x * blockDim.x + threadIdx.x;
    if (idx >= M_TOT * D_INP / 2) return;
    int m = idx / (D_INP / 2), i = (idx % (D_INP / 2)) * 2;
    float2 v = *(const float2*)(u + (size_t)m * D_INP + i);
    __half2 h = __floats2half2_rn(v.x, v.y);
    *(__half2*)(g_A2 + (size_t)m * KCAT + NBU + i) = h;
}

// ---------------- shared GEMM mainloop ----------------
// CTA tile 128x128, BK=32, 8 warps (2x4), warp tile 64x32, mma.m16n8k16.
// C = A[m,k] * (Bh+Bl)[n,k]^T ; acc left in registers.
#define BK       32
#define PADK     40                       // padded k-stride (elems)
#define TILE_B   (128 * PADK * 2)         // 10240 B per tile
#define STAGES   4
#define SMEM_GEMM (STAGES * 3 * TILE_B)   // 122880 B

__device__ __forceinline__ void gemm_mainloop(
    uint32_t sb, const __half* A0, const __half* Bh0, const __half* Bl0,
    int K, int lda, int ldb, float acc[4][4][4],
    int tid, int wm, int wn, int lid) {

    const int NC = K / BK;

    auto issue_load = [&](int c) {
        const int s = c % STAGES;
        const uint32_t stb = sb + s * 3 * TILE_B;
        const int k0 = c * BK;
#pragma unroll
        for (int r = 0; r < 2; r++) {
            int idx = tid + r * 256;                 // 0..511
            int row = idx >> 2, ch = idx & 3;
            uint32_t soff = (uint32_t)(row * (PADK * 2) + ch * 16);
            size_t goff = (size_t)row * lda + k0 + ch * 8;
            CP_ASYNC16(stb + soff, A0 + goff);
        }
#pragma unroll
        for (int r = 0; r < 2; r++) {
            int idx = tid + r * 256;
            int row = idx >> 2, ch = idx & 3;
            uint32_t soff = (uint32_t)(row * (PADK * 2) + ch * 16);
            size_t goff = (size_t)row * ldb + k0 + ch * 8;
            CP_ASYNC16(stb + TILE_B + soff, Bh0 + goff);
            CP_ASYNC16(stb + 2 * TILE_B + soff, Bl0 + goff);
        }
        CP_COMMIT();
    };

    const int aRow = lid & 15;
    const int aCol = (lid >> 4) << 3;
    const int bRow = (lid & 7) + ((lid >> 4) << 3);
    const int bCol = ((lid >> 3) & 1) << 3;

    issue_load(0);
    issue_load(1);
    issue_load(2);

    for (int c = 0; c < NC; c++) {
        CP_WAIT2();
        __syncthreads();
        if (c + 3 < NC) issue_load(c + 3);
        else            CP_COMMIT();

        const uint32_t stb = sb + (c % STAGES) * 3 * TILE_B;
        const uint32_t sA  = stb;
        const uint32_t sBh = stb + TILE_B;
        const uint32_t sBl = stb + 2 * TILE_B;

#pragma unroll
        for (int kk = 0; kk < BK; kk += 16) {
            uint32_t a[4][4], bh[2][4], bl[2][4];
#pragma unroll
            for (int mf = 0; mf < 4; mf++) {
                uint32_t ad = sA + (uint32_t)((wm * 64 + mf * 16 + aRow) * (PADK * 2) + (kk + aCol) * 2);
                LDSM4(a[mf][0], a[mf][1], a[mf][2], a[mf][3], ad);
            }
#pragma unroll
            for (int p = 0; p < 2; p++) {
                uint32_t bd = sBh + (uint32_t)((wn * 32 + p * 16 + bRow) * (PADK * 2) + (kk + bCol) * 2);
                LDSM4(bh[p][0], bh[p][1], bh[p][2], bh[p][3], bd);
            }
#pragma unroll
            for (int p = 0; p < 2; p++) {
                uint32_t bd = sBl + (uint32_t)((wn * 32 + p * 16 + bRow) * (PADK * 2) + (kk + bCol) * 2);
                LDSM4(bl[p][0], bl[p][1], bl[p][2], bl[p][3], bd);
            }
#pragma unroll
            for (int mf = 0; mf < 4; mf++)
#pragma unroll
                for (int nf = 0; nf < 4; nf++)
                    MMA16816(acc[mf][nf], a[mf], bh[nf >> 1][(nf & 1) * 2], bh[nf >> 1][(nf & 1) * 2 + 1]);
#pragma unroll
            for (int mf = 0; mf < 4; mf++)
#pragma unroll
                for (int nf = 0; nf < 4; nf++)
                    MMA16816(acc[mf][nf], a[mf], bl[nf >> 1][(nf & 1) * 2], bl[nf >> 1][(nf & 1) * 2 + 1]);
        }
        __syncthreads();
    }
    CP_WAIT0();
}

// ---------------- GEMM1 + fused chunk-local scan ----------------
// Computes Bu tile (128 t-rows x 128 interleaved n-cols), scans it in smem,
// writes x_local fp16 into A2 and the chunk final into g_F.
#define SCAN_STRIDE 136

__global__ __launch_bounds__(256, 1)
void gemm1_scan(const __half* __restrict__ A,
                const __half* __restrict__ Bh,
                const __half* __restrict__ Bl) {
    extern __shared__ char smem[];
    const uint32_t sb = smem_u32(smem);
    const int tid = threadIdx.x;
    const int wid = tid >> 5, lid = tid & 31;
    const int m0 = blockIdx.y * 128;
    const int n0 = blockIdx.x * 128;
    const int wm = wid >> 2, wn = wid & 3;

    float acc[4][4][4];
#pragma unroll
    for (int i = 0; i < 4; i++)
#pragma unroll
        for (int j = 0; j < 4; j++)
#pragma unroll
            for (int q = 0; q < 4; q++) acc[i][j][q] = 0.0f;

    gemm_mainloop(sb, A + (size_t)m0 * KCAT, Bh + (size_t)n0 * D_INP,
                  Bl + (size_t)n0 * D_INP, D_INP, KCAT, D_INP,
                  acc, tid, wm, wn, lid);

    __syncthreads();            // pipeline smem dead, reuse for scan buffer

    float* sc = (float*)smem;   // [128][SCAN_STRIDE]
    const int gid = lid >> 2, tig = lid & 3;
#pragma unroll
    for (int mf = 0; mf < 4; mf++) {
        const int row = wm * 64 + mf * 16 + gid;
#pragma unroll
        for (int nf = 0; nf < 4; nf++) {
            const int col = wn * 32 + nf * 8 + tig * 2;
            *(float2*)(sc + row * SCAN_STRIDE + col) =
                make_float2(acc[mf][nf][0], acc[mf][nf][1]);
            *(float2*)(sc + (row + 8) * SCAN_STRIDE + col) =
                make_float2(acc[mf][nf][2], acc[mf][nf][3]);
        }
    }
    __syncthreads();

    // chunk-local complex scan: 64 complex pairs in this tile
    if (tid < 64) {
        const int np = (n0 >> 1) + tid;       // global state index
        const float2 lam = g_lam[np];
        const int b = m0 >> 12;               // / T_LEN
        const int c = (m0 & (T_LEN - 1)) >> 7;  // / CHUNK
        float xr = 0.0f, xi = 0.0f;
        __half* out = g_A2 + (size_t)m0 * KCAT + 2 * np;
#pragma unroll 4
        for (int t = 0; t < CHUNK; t++) {
            float2 bu = *(const float2*)(sc + t * SCAN_STRIDE + 2 * tid);
            float nxr = fmaf(lam.x, xr, fmaf(-lam.y, xi, bu.x));
            float nxi = fmaf(lam.x, xi, fmaf(lam.y, xr, bu.y));
            xr = nxr; xi = nxi;
            *(__half2*)(out + (size_t)t * KCAT) = __floats2half2_rn(xr, xi);
        }
        g_F[(b * NCHUNK + c) * N_ST + np] = make_float2(xr, xi);
    }
}

// ---------------- generic GEMM (for GEMM2) ----------------
__global__ __launch_bounds__(256, 1)
void gemm_wsplit_mma(const __half* __restrict__ A,
                     const __half* __restrict__ Bh,
                     const __half* __restrict__ Bl,
                     float* __restrict__ C,
                     int K, int lda, int ldb, int ldc) {
    extern __shared__ char smem[];
    const uint32_t sb = smem_u32(smem);
    const int tid = threadIdx.x;
    const int wid = tid >> 5, lid = tid & 31;
    const int m0 = blockIdx.y * 128;
    const int n0 = blockIdx.x * 128;
    const int wm = wid >> 2, wn = wid & 3;

    float acc[4][4][4];
#pragma unroll
    for (int i = 0; i < 4; i++)
#pragma unroll
        for (int j = 0; j < 4; j++)
#pragma unroll
            for (int q = 0; q < 4; q++) acc[i][j][q] = 0.0f;

    gemm_mainloop(sb, A + (size_t)m0 * lda, Bh + (size_t)n0 * ldb,
                  Bl + (size_t)n0 * ldb, K, lda, ldb,
                  acc, tid, wm, wn, lid);

    const int gid = lid >> 2, tig = lid & 3;
#pragma unroll
    for (int mf = 0; mf < 4; mf++) {
        const int row = m0 + wm * 64 + mf * 16 + gid;
#pragma unroll
        for (int nf = 0; nf < 4; nf++) {
            const int col = n0 + wn * 32 + nf * 8 + tig * 2;
            *(float2*)(C + (size_t)row * ldc + col) =
                make_float2(acc[mf][nf][0], acc[mf][nf][1]);
            *(float2*)(C + (size_t)(row + 8) * ldc + col) =
                make_float2(acc[mf][nf][2], acc[mf][nf][3]);
        }
    }
}

// ---------------- chunk-level prefix over finals ----------------
__global__ void k_chunk_prefix() {
    int id = blockIdx.x * blockDim.x + threadIdx.x;
    if (id >= B_SZ * N_ST) return;
    int n = id & (N_ST - 1);
    int b = id >> 9;
    float2 lamL = g_lamL[n];
    float sr = 0.0f, si = 0.0f;
#pragma unroll
    for (int c = 0; c < NCHUNK; c++) {
        int idx = (b * NCHUNK + c) * N_ST + n;
        g_carry[idx] = make_float2(sr, si);
        float2 f = g_F[idx];
        float nsr = fmaf(lamL.x, sr, fmaf(-lamL.y, si, f.x));
        float nsi = fmaf(lamL.x, si, fmaf(lamL.y, sr, f.y));
        sr = nsr; si = nsi;
    }
}

// ---------------- carry correction: x_t += lam^{t+1} * carry ----------------
__global__ void k_correct() {
    int id = blockIdx.x * blockDim.x + threadIdx.x;
    if (id >= B_SZ * NCHUNK * N_ST) return;
    int np = id & (N_ST - 1);
    int c = (id >> 9) & (NCHUNK - 1);
    int b = id >> 14;
    if (c == 0) return;                       // carry is zero for chunk 0
    float2 carry = g_carry[id];
    float2 lam = g_lam[np];
    float fr = carry.x, fi = carry.y;
    __half* xp = g_A2 + ((size_t)(b * T_LEN + c * CHUNK)) * KCAT + 2 * np;
#pragma unroll 4
    for (int t = 0; t < CHUNK; t++) {
        float nfr = fr * lam.x - fi * lam.y;
        float nfi = fr * lam.y + fi * lam.x;
        fr = nfr; fi = nfi;
        __half2 v = *(__half2*)(xp + (size_t)t * KCAT);
        float2 xv = __half22float2(v);
        *(__half2*)(xp + (size_t)t * KCAT) =
            __floats2half2_rn(xv.x + fr, xv.y + fi);
    }
}

// ---------------- launch ----------------
extern "C" void kernel_launch(void* const* d_in, const int* in_sizes, int n_in,
                              void* d_out, int out_size) {
    const float* u_in      = (const float*)d_in[0];
    const float* nu_log    = (const float*)d_in[1];
    const float* theta_log = (const float*)d_in[2];
    const float* gamma_log = (const float*)d_in[3];
    const float* B_real    = (const float*)d_in[4];
    const float* B_imag    = (const float*)d_in[5];
    const float* C_real    = (const float*)d_in[6];
    const float* C_imag    = (const float*)d_in[7];
    const float* Dm        = (const float*)d_in[8];
    float* y = (float*)d_out;

    __half *a2, *b1h, *b1l, *w2h, *w2l;
    cudaGetSymbolAddress((void**)&a2,  g_A2);
    cudaGetSymbolAddress((void**)&b1h, g_B1h);
    cudaGetSymbolAddress((void**)&b1l, g_B1l);
    cudaGetSymbolAddress((void**)&w2h, g_W2h);
    cudaGetSymbolAddress((void**)&w2l, g_W2l);

    cudaFuncSetAttribute(gemm1_scan,
                         cudaFuncAttributeMaxDynamicSharedMemorySize, SMEM_GEMM);
    cudaFuncSetAttribute(gemm_wsplit_mma,
                         cudaFuncAttributeMaxDynamicSharedMemorySize, SMEM_GEMM);

    // setup / splits
    k_setup<<<2, 256>>>(nu_log, theta_log);
    k_splitB<<<(NBU * D_INP + 255) / 256, 256>>>(gamma_log, B_real, B_imag);
    k_buildW2<<<(D_OUTP * KCAT + 255) / 256, 256>>>(C_real, C_imag, Dm);
    k_cvtU<<<(M_TOT * D_INP / 2 + 255) / 256, 256>>>(u_in);

    // GEMM1 + chunk-local scan: writes X_local (fp16) into A2 and chunk finals
    {
        dim3 grid(NBU / 128, M_TOT / 128);
        gemm1_scan<<<grid, 256, SMEM_GEMM>>>(a2 + NBU, b1h, b1l);
    }

    // chunk prefix + carry correction
    k_chunk_prefix<<<(B_SZ * N_ST + 255) / 256, 256>>>();
    k_correct<<<(B_SZ * NCHUNK * N_ST + 255) / 256, 256>>>();

    // GEMM 2: y[M, 256] = [X | u] @ W2^T, K=1280
    {
        dim3 grid(D_OUTP / 128, M_TOT / 128);
        gemm_wsplit_mma<<<grid, 256, SMEM_GEMM>>>(a2, w2h, w2l,
                                                  y, KCAT, KCAT, KCAT, D_OUTP);
    }
}

// round 6
// speedup vs baseline: 3.8517x; 1.4543x over previous
#include <cuda_runtime.h>
#include <cuda_fp16.h>
#include <cstdint>

// ---------------- problem constants ----------------
#define B_SZ   8
#define T_LEN  4096
#define D_INP  256
#define D_OUTP 256
#define N_ST   512
#define M_TOT  (B_SZ * T_LEN)      // 32768
#define NBU    (2 * N_ST)          // 1024
#define KCAT   (NBU + D_INP)       // 1280
#define CHUNK  128
#define NCHUNK (T_LEN / CHUNK)     // 32

// ---------------- device scratch ----------------
// A2 layout: cols [0,1024) = X interleaved (2n = xr_n, 2n+1 = xi_n), cols [1024,1280) = u
__device__ __half g_A2[(size_t)M_TOT * KCAT];
__device__ __half g_B1[NBU * D_INP];             // gamma-scaled B, interleaved rows
__device__ __half g_W2[D_OUTP * KCAT];           // K-interleaved [2Cr/-2Ci | D]
__device__ float2 g_lam [N_ST];
__device__ float2 g_lamL[N_ST];
__device__ float2 g_F    [B_SZ * NCHUNK * N_ST];
__device__ float2 g_carry[B_SZ * NCHUNK * N_ST];

// ---------------- helpers ----------------
__device__ __forceinline__ uint32_t smem_u32(const void* p) {
    uint32_t a;
    asm("{ .reg .u64 t; cvta.to.shared.u64 t, %1; cvt.u32.u64 %0, t; }" : "=r"(a) : "l"(p));
    return a;
}

#define CP_ASYNC16(dst, src) \
    asm volatile("cp.async.cg.shared.global [%0], [%1], 16;" :: "r"(dst), "l"(src))
#define CP_COMMIT() asm volatile("cp.async.commit_group;")
#define CP_WAIT2()  asm volatile("cp.async.wait_group 2;")
#define CP_WAIT0()  asm volatile("cp.async.wait_group 0;")

#define LDSM4(r0, r1, r2, r3, addr) \
    asm volatile("ldmatrix.sync.aligned.m8n8.x4.shared.b16 {%0,%1,%2,%3}, [%4];" \
        : "=r"(r0), "=r"(r1), "=r"(r2), "=r"(r3) : "r"(addr))

#define MMA16816(d, a, b0, b1) \
    asm volatile("mma.sync.aligned.m16n8k16.row.col.f32.f16.f16.f32 " \
        "{%0,%1,%2,%3}, {%4,%5,%6,%7}, {%8,%9}, {%0,%1,%2,%3};" \
        : "+f"(d[0]), "+f"(d[1]), "+f"(d[2]), "+f"(d[3]) \
        : "r"(a[0]), "r"(a[1]), "r"(a[2]), "r"(a[3]), "r"(b0), "r"(b1))

// ---------------- setup kernels ----------------
__global__ void k_setup(const float* __restrict__ nu_log,
                        const float* __restrict__ theta_log) {
    int n = blockIdx.x * blockDim.x + threadIdx.x;
    if (n >= N_ST) return;
    float lm = expf(-expf(nu_log[n]));
    float th = expf(theta_log[n]);
    float2 lam = make_float2(lm * cosf(th), lm * sinf(th));
    g_lam[n] = lam;
    float2 p = lam;
#pragma unroll
    for (int i = 0; i < 7; i++) {
        float2 q;
        q.x = p.x * p.x - p.y * p.y;
        q.y = 2.0f * p.x * p.y;
        p = q;
    }
    g_lamL[n] = p;
}

// interleaved rows: row 2n = gamma*Br[n], row 2n+1 = gamma*Bi[n]
__global__ void k_cvtB(const float* __restrict__ gamma_log,
                       const float* __restrict__ Br,
                       const float* __restrict__ Bi) {
    int idx = blockIdx.x * blockDim.x + threadIdx.x;
    if (idx >= NBU * D_INP) return;
    int nn = idx / D_INP, i = idx % D_INP;
    int n = nn >> 1;
    float g = expf(gamma_log[n]);
    float v = g * (((nn & 1) == 0) ? Br[n * D_INP + i] : Bi[n * D_INP + i]);
    g_B1[idx] = __float2half_rn(v);
}

// K-interleaved weights: k=2n -> 2Cr[o][n], k=2n+1 -> -2Ci[o][n], k>=1024 -> D
__global__ void k_buildW2(const float* __restrict__ Cr,
                          const float* __restrict__ Ci,
                          const float* __restrict__ Dm) {
    int idx = blockIdx.x * blockDim.x + threadIdx.x;
    if (idx >= D_OUTP * KCAT) return;
    int o = idx / KCAT, k = idx % KCAT;
    float v;
    if (k < NBU) {
        int n = k >> 1;
        v = ((k & 1) == 0) ? 2.0f * Cr[o * N_ST + n] : -2.0f * Ci[o * N_ST + n];
    } else {
        v = Dm[o * D_INP + (k - NBU)];
    }
    g_W2[idx] = __float2half_rn(v);
}

__global__ void k_cvtU(const float* __restrict__ u) {
    int idx = blockIdx.x * blockDim.x + threadIdx.x;
    if (idx >= M_TOT * D_INP / 2) return;
    int m = idx / (D_INP / 2), i = (idx % (D_INP / 2)) * 2;
    float2 v = *(const float2*)(u + (size_t)m * D_INP + i);
    __half2 h = __floats2half2_rn(v.x, v.y);
    *(__half2*)(g_A2 + (size_t)m * KCAT + NBU + i) = h;
}

// ---------------- shared GEMM mainloop (plain fp16, single pass) ----------------
// CTA tile 128x128, BK=32, 8 warps (2x4), warp tile 64x32, mma.m16n8k16.
#define BK       32
#define PADK     40                       // padded k-stride (elems)
#define TILE_B   (128 * PADK * 2)         // 10240 B per tile
#define STAGES   4
#define SMEM_GEMM (STAGES * 2 * TILE_B)   // 81920 B

__device__ __forceinline__ void gemm_mainloop(
    uint32_t sb, const __half* A0, const __half* B0,
    int K, int lda, int ldb, float acc[4][4][4],
    int tid, int wm, int wn, int lid) {

    const int NC = K / BK;

    auto issue_load = [&](int c) {
        const int s = c % STAGES;
        const uint32_t stb = sb + s * 2 * TILE_B;
        const int k0 = c * BK;
#pragma unroll
        for (int r = 0; r < 2; r++) {
            int idx = tid + r * 256;                 // 0..511
            int row = idx >> 2, ch = idx & 3;
            uint32_t soff = (uint32_t)(row * (PADK * 2) + ch * 16);
            CP_ASYNC16(stb + soff, A0 + (size_t)row * lda + k0 + ch * 8);
            CP_ASYNC16(stb + TILE_B + soff, B0 + (size_t)row * ldb + k0 + ch * 8);
        }
        CP_COMMIT();
    };

    const int aRow = lid & 15;
    const int aCol = (lid >> 4) << 3;
    const int bRow = (lid & 7) + ((lid >> 4) << 3);
    const int bCol = ((lid >> 3) & 1) << 3;

    issue_load(0);
    issue_load(1);
    issue_load(2);

    for (int c = 0; c < NC; c++) {
        CP_WAIT2();
        __syncthreads();
        if (c + 3 < NC) issue_load(c + 3);
        else            CP_COMMIT();

        const uint32_t stb = sb + (c % STAGES) * 2 * TILE_B;
        const uint32_t sA = stb;
        const uint32_t sB = stb + TILE_B;

#pragma unroll
        for (int kk = 0; kk < BK; kk += 16) {
            uint32_t a[4][4], b[2][4];
#pragma unroll
            for (int mf = 0; mf < 4; mf++) {
                uint32_t ad = sA + (uint32_t)((wm * 64 + mf * 16 + aRow) * (PADK * 2) + (kk + aCol) * 2);
                LDSM4(a[mf][0], a[mf][1], a[mf][2], a[mf][3], ad);
            }
#pragma unroll
            for (int p = 0; p < 2; p++) {
                uint32_t bd = sB + (uint32_t)((wn * 32 + p * 16 + bRow) * (PADK * 2) + (kk + bCol) * 2);
                LDSM4(b[p][0], b[p][1], b[p][2], b[p][3], bd);
            }
#pragma unroll
            for (int mf = 0; mf < 4; mf++)
#pragma unroll
                for (int nf = 0; nf < 4; nf++)
                    MMA16816(acc[mf][nf], a[mf], b[nf >> 1][(nf & 1) * 2], b[nf >> 1][(nf & 1) * 2 + 1]);
        }
        __syncthreads();
    }
    CP_WAIT0();
}

// ---------------- GEMM1 + fused chunk-local scan ----------------
#define SCAN_STRIDE 136

__global__ __launch_bounds__(256, 1)
void gemm1_scan(const __half* __restrict__ A,
                const __half* __restrict__ B) {
    extern __shared__ char smem[];
    const uint32_t sb = smem_u32(smem);
    const int tid = threadIdx.x;
    const int wid = tid >> 5, lid = tid & 31;
    const int m0 = blockIdx.y * 128;
    const int n0 = blockIdx.x * 128;
    const int wm = wid >> 2, wn = wid & 3;

    float acc[4][4][4];
#pragma unroll
    for (int i = 0; i < 4; i++)
#pragma unroll
        for (int j = 0; j < 4; j++)
#pragma unroll
            for (int q = 0; q < 4; q++) acc[i][j][q] = 0.0f;

    gemm_mainloop(sb, A + (size_t)m0 * KCAT, B + (size_t)n0 * D_INP,
                  D_INP, KCAT, D_INP, acc, tid, wm, wn, lid);

    __syncthreads();            // pipeline smem dead, reuse for scan buffer

    float* sc = (float*)smem;   // [128][SCAN_STRIDE]
    const int gid = lid >> 2, tig = lid & 3;
#pragma unroll
    for (int mf = 0; mf < 4; mf++) {
        const int row = wm * 64 + mf * 16 + gid;
#pragma unroll
        for (int nf = 0; nf < 4; nf++) {
            const int col = wn * 32 + nf * 8 + tig * 2;
            *(float2*)(sc + row * SCAN_STRIDE + col) =
                make_float2(acc[mf][nf][0], acc[mf][nf][1]);
            *(float2*)(sc + (row + 8) * SCAN_STRIDE + col) =
                make_float2(acc[mf][nf][2], acc[mf][nf][3]);
        }
    }
    __syncthreads();

    // chunk-local complex scan: 64 complex pairs in this tile
    if (tid < 64) {
        const int np = (n0 >> 1) + tid;       // global state index
        const float2 lam = g_lam[np];
        const int b = m0 >> 12;               // / T_LEN
        const int c = (m0 & (T_LEN - 1)) >> 7;  // / CHUNK
        float xr = 0.0f, xi = 0.0f;
        __half* out = g_A2 + (size_t)m0 * KCAT + 2 * np;
#pragma unroll 4
        for (int t = 0; t < CHUNK; t++) {
            float2 bu = *(const float2*)(sc + t * SCAN_STRIDE + 2 * tid);
            float nxr = fmaf(lam.x, xr, fmaf(-lam.y, xi, bu.x));
            float nxi = fmaf(lam.x, xi, fmaf(lam.y, xr, bu.y));
            xr = nxr; xi = nxi;
            *(__half2*)(out + (size_t)t * KCAT) = __floats2half2_rn(xr, xi);
        }
        g_F[(b * NCHUNK + c) * N_ST + np] = make_float2(xr, xi);
    }
}

// ---------------- generic GEMM (for GEMM2) ----------------
__global__ __launch_bounds__(256, 1)
void gemm_fp16_mma(const __half* __restrict__ A,
                   const __half* __restrict__ B,
                   float* __restrict__ C,
                   int K, int lda, int ldb, int ldc) {
    extern __shared__ char smem[];
    const uint32_t sb = smem_u32(smem);
    const int tid = threadIdx.x;
    const int wid = tid >> 5, lid = tid & 31;
    const int m0 = blockIdx.y * 128;
    const int n0 = blockIdx.x * 128;
    const int wm = wid >> 2, wn = wid & 3;

    float acc[4][4][4];
#pragma unroll
    for (int i = 0; i < 4; i++)
#pragma unroll
        for (int j = 0; j < 4; j++)
#pragma unroll
            for (int q = 0; q < 4; q++) acc[i][j][q] = 0.0f;

    gemm_mainloop(sb, A + (size_t)m0 * lda, B + (size_t)n0 * ldb,
                  K, lda, ldb, acc, tid, wm, wn, lid);

    const int gid = lid >> 2, tig = lid & 3;
#pragma unroll
    for (int mf = 0; mf < 4; mf++) {
        const int row = m0 + wm * 64 + mf * 16 + gid;
#pragma unroll
        for (int nf = 0; nf < 4; nf++) {
            const int col = n0 + wn * 32 + nf * 8 + tig * 2;
            *(float2*)(C + (size_t)row * ldc + col) =
                make_float2(acc[mf][nf][0], acc[mf][nf][1]);
            *(float2*)(C + (size_t)(row + 8) * ldc + col) =
                make_float2(acc[mf][nf][2], acc[mf][nf][3]);
        }
    }
}

// ---------------- chunk-level prefix over finals ----------------
__global__ void k_chunk_prefix() {
    int id = blockIdx.x * blockDim.x + threadIdx.x;
    if (id >= B_SZ * N_ST) return;
    int n = id & (N_ST - 1);
    int b = id >> 9;
    float2 lamL = g_lamL[n];
    float sr = 0.0f, si = 0.0f;
#pragma unroll
    for (int c = 0; c < NCHUNK; c++) {
        int idx = (b * NCHUNK + c) * N_ST + n;
        g_carry[idx] = make_float2(sr, si);
        float2 f = g_F[idx];
        float nsr = fmaf(lamL.x, sr, fmaf(-lamL.y, si, f.x));
        float nsi = fmaf(lamL.x, si, fmaf(lamL.y, sr, f.y));
        sr = nsr; si = nsi;
    }
}

// ---------------- carry correction: x_t += lam^{t+1} * carry ----------------
__global__ void k_correct() {
    int id = blockIdx.x * blockDim.x + threadIdx.x;
    if (id >= B_SZ * NCHUNK * N_ST) return;
    int np = id & (N_ST - 1);
    int c = (id >> 9) & (NCHUNK - 1);
    int b = id >> 14;
    if (c == 0) return;                       // carry is zero for chunk 0
    float2 carry = g_carry[id];
    float2 lam = g_lam[np];
    float fr = carry.x, fi = carry.y;
    __half* xp = g_A2 + ((size_t)(b * T_LEN + c * CHUNK)) * KCAT + 2 * np;
#pragma unroll 4
    for (int t = 0; t < CHUNK; t++) {
        float nfr = fr * lam.x - fi * lam.y;
        float nfi = fr * lam.y + fi * lam.x;
        fr = nfr; fi = nfi;
        __half2 v = *(__half2*)(xp + (size_t)t * KCAT);
        float2 xv = __half22float2(v);
        *(__half2*)(xp + (size_t)t * KCAT) =
            __floats2half2_rn(xv.x + fr, xv.y + fi);
    }
}

// ---------------- launch ----------------
extern "C" void kernel_launch(void* const* d_in, const int* in_sizes, int n_in,
                              void* d_out, int out_size) {
    const float* u_in      = (const float*)d_in[0];
    const float* nu_log    = (const float*)d_in[1];
    const float* theta_log = (const float*)d_in[2];
    const float* gamma_log = (const float*)d_in[3];
    const float* B_real    = (const float*)d_in[4];
    const float* B_imag    = (const float*)d_in[5];
    const float* C_real    = (const float*)d_in[6];
    const float* C_imag    = (const float*)d_in[7];
    const float* Dm        = (const float*)d_in[8];
    float* y = (float*)d_out;

    __half *a2, *b1, *w2;
    cudaGetSymbolAddress((void**)&a2, g_A2);
    cudaGetSymbolAddress((void**)&b1, g_B1);
    cudaGetSymbolAddress((void**)&w2, g_W2);

    cudaFuncSetAttribute(gemm1_scan,
                         cudaFuncAttributeMaxDynamicSharedMemorySize, SMEM_GEMM);
    cudaFuncSetAttribute(gemm_fp16_mma,
                         cudaFuncAttributeMaxDynamicSharedMemorySize, SMEM_GEMM);

    // setup / conversions
    k_setup<<<2, 256>>>(nu_log, theta_log);
    k_cvtB<<<(NBU * D_INP + 255) / 256, 256>>>(gamma_log, B_real, B_imag);
    k_buildW2<<<(D_OUTP * KCAT + 255) / 256, 256>>>(C_real, C_imag, Dm);
    k_cvtU<<<(M_TOT * D_INP / 2 + 255) / 256, 256>>>(u_in);

    // GEMM1 + chunk-local scan: writes X_local (fp16) into A2 and chunk finals
    {
        dim3 grid(NBU / 128, M_TOT / 128);
        gemm1_scan<<<grid, 256, SMEM_GEMM>>>(a2 + NBU, b1);
    }

    // chunk prefix + carry correction
    k_chunk_prefix<<<(B_SZ * N_ST + 255) / 256, 256>>>();
    k_correct<<<(B_SZ * NCHUNK * N_ST + 255) / 256, 256>>>();

    // GEMM 2: y[M, 256] = [X | u] @ W2^T, K=1280
    {
        dim3 grid(D_OUTP / 128, M_TOT / 128);
        gemm_fp16_mma<<<grid, 256, SMEM_GEMM>>>(a2, w2, y, KCAT, KCAT, KCAT, D_OUTP);
    }
}

// round 7
// speedup vs baseline: 4.2544x; 1.1045x over previous
#include <cuda_runtime.h>
#include <cuda_fp16.h>
#include <cstdint>

// ---------------- problem constants ----------------
#define B_SZ   8
#define T_LEN  4096
#define D_INP  256
#define D_OUTP 256
#define N_ST   512
#define M_TOT  (B_SZ * T_LEN)      // 32768
#define NBU    (2 * N_ST)          // 1024
#define KCAT   (NBU + D_INP)       // 1280
#define CHUNK  128
#define NCHUNK (T_LEN / CHUNK)     // 32

// ---------------- device scratch ----------------
// A2 layout: cols [0,1024) = X interleaved (2n = xr_n, 2n+1 = xi_n), cols [1024,1280) = u
__device__ __half g_A2[(size_t)M_TOT * KCAT];
__device__ __half g_B1[NBU * D_INP];             // gamma-scaled B, interleaved rows
__device__ __half g_W2[D_OUTP * KCAT];           // K-interleaved [2Cr/-2Ci | D]
__device__ float2 g_lam [N_ST];
__device__ float2 g_lamL[N_ST];
__device__ float2 g_F    [B_SZ * NCHUNK * N_ST];
__device__ float2 g_carry[B_SZ * NCHUNK * N_ST];

// ---------------- helpers ----------------
__device__ __forceinline__ uint32_t smem_u32(const void* p) {
    uint32_t a;
    asm("{ .reg .u64 t; cvta.to.shared.u64 t, %1; cvt.u32.u64 %0, t; }" : "=r"(a) : "l"(p));
    return a;
}

#define CP_ASYNC16(dst, src) \
    asm volatile("cp.async.cg.shared.global [%0], [%1], 16;" :: "r"(dst), "l"(src))
#define CP_COMMIT() asm volatile("cp.async.commit_group;")
#define CP_WAIT2()  asm volatile("cp.async.wait_group 2;")
#define CP_WAIT0()  asm volatile("cp.async.wait_group 0;")

#define LDSM4(r0, r1, r2, r3, addr) \
    asm volatile("ldmatrix.sync.aligned.m8n8.x4.shared.b16 {%0,%1,%2,%3}, [%4];" \
        : "=r"(r0), "=r"(r1), "=r"(r2), "=r"(r3) : "r"(addr))

#define MMA16816(d, a, b0, b1) \
    asm volatile("mma.sync.aligned.m16n8k16.row.col.f32.f16.f16.f32 " \
        "{%0,%1,%2,%3}, {%4,%5,%6,%7}, {%8,%9}, {%0,%1,%2,%3};" \
        : "+f"(d[0]), "+f"(d[1]), "+f"(d[2]), "+f"(d[3]) \
        : "r"(a[0]), "r"(a[1]), "r"(a[2]), "r"(a[3]), "r"(b0), "r"(b1))

// ---------------- setup kernels ----------------
__global__ void k_setup(const float* __restrict__ nu_log,
                        const float* __restrict__ theta_log) {
    int n = blockIdx.x * blockDim.x + threadIdx.x;
    if (n >= N_ST) return;
    float lm = expf(-expf(nu_log[n]));
    float th = expf(theta_log[n]);
    float2 lam = make_float2(lm * cosf(th), lm * sinf(th));
    g_lam[n] = lam;
    float2 p = lam;
#pragma unroll
    for (int i = 0; i < 7; i++) {
        float2 q;
        q.x = p.x * p.x - p.y * p.y;
        q.y = 2.0f * p.x * p.y;
        p = q;
    }
    g_lamL[n] = p;
}

// interleaved rows: row 2n = gamma*Br[n], row 2n+1 = gamma*Bi[n]
__global__ void k_cvtB(const float* __restrict__ gamma_log,
                       const float* __restrict__ Br,
                       const float* __restrict__ Bi) {
    int idx = blockIdx.x * blockDim.x + threadIdx.x;
    if (idx >= NBU * D_INP) return;
    int nn = idx / D_INP, i = idx % D_INP;
    int n = nn >> 1;
    float g = expf(gamma_log[n]);
    float v = g * (((nn & 1) == 0) ? Br[n * D_INP + i] : Bi[n * D_INP + i]);
    g_B1[idx] = __float2half_rn(v);
}

// K-interleaved weights: k=2n -> 2Cr[o][n], k=2n+1 -> -2Ci[o][n], k>=1024 -> D
__global__ void k_buildW2(const float* __restrict__ Cr,
                          const float* __restrict__ Ci,
                          const float* __restrict__ Dm) {
    int idx = blockIdx.x * blockDim.x + threadIdx.x;
    if (idx >= D_OUTP * KCAT) return;
    int o = idx / KCAT, k = idx % KCAT;
    float v;
    if (k < NBU) {
        int n = k >> 1;
        v = ((k & 1) == 0) ? 2.0f * Cr[o * N_ST + n] : -2.0f * Ci[o * N_ST + n];
    } else {
        v = Dm[o * D_INP + (k - NBU)];
    }
    g_W2[idx] = __float2half_rn(v);
}

__global__ void k_cvtU(const float* __restrict__ u) {
    int idx = blockIdx.x * blockDim.x + threadIdx.x;
    if (idx >= M_TOT * D_INP / 2) return;
    int m = idx / (D_INP / 2), i = (idx % (D_INP / 2)) * 2;
    float2 v = *(const float2*)(u + (size_t)m * D_INP + i);
    __half2 h = __floats2half2_rn(v.x, v.y);
    *(__half2*)(g_A2 + (size_t)m * KCAT + NBU + i) = h;
}

// ---------------- GEMM mainloop: CTA tile 128(M) x 256(N), BK=32 ----------------
// 8 warps as 2(m) x 4(n); warp tile 64x64; mma.m16n8k16; acc[4][8][4].
#define BK       32
#define PADK     40                       // padded k-stride (elems)
#define TILE_A_B (128 * PADK * 2)         // 10240 B
#define TILE_B_B (256 * PADK * 2)         // 20480 B
#define STAGE_B  (TILE_A_B + TILE_B_B)    // 30720 B
#define STAGES   4
#define SMEM_GEMM (STAGES * STAGE_B)      // 122880 B

__device__ __forceinline__ void gemm_mainloop(
    uint32_t sb, const __half* A0, const __half* B0,
    int K, int lda, int ldb, float acc[4][8][4],
    int tid, int wm, int wn, int lid) {

    const int NC = K / BK;

    auto issue_load = [&](int c) {
        const int s = c % STAGES;
        const uint32_t stb = sb + s * STAGE_B;
        const int k0 = c * BK;
#pragma unroll
        for (int r = 0; r < 2; r++) {                // A: 512 chunks
            int idx = tid + r * 256;
            int row = idx >> 2, ch = idx & 3;
            uint32_t soff = (uint32_t)(row * (PADK * 2) + ch * 16);
            CP_ASYNC16(stb + soff, A0 + (size_t)row * lda + k0 + ch * 8);
        }
#pragma unroll
        for (int r = 0; r < 4; r++) {                // B: 1024 chunks
            int idx = tid + r * 256;
            int row = idx >> 2, ch = idx & 3;
            uint32_t soff = (uint32_t)(row * (PADK * 2) + ch * 16);
            CP_ASYNC16(stb + TILE_A_B + soff, B0 + (size_t)row * ldb + k0 + ch * 8);
        }
        CP_COMMIT();
    };

    const int aRow = lid & 15;
    const int aCol = (lid >> 4) << 3;
    const int bRow = (lid & 7) + ((lid >> 4) << 3);
    const int bCol = ((lid >> 3) & 1) << 3;

    issue_load(0);
    issue_load(1);
    issue_load(2);

    for (int c = 0; c < NC; c++) {
        CP_WAIT2();
        __syncthreads();
        if (c + 3 < NC) issue_load(c + 3);
        else            CP_COMMIT();

        const uint32_t stb = sb + (c % STAGES) * STAGE_B;
        const uint32_t sA = stb;
        const uint32_t sB = stb + TILE_A_B;

#pragma unroll
        for (int kk = 0; kk < BK; kk += 16) {
            uint32_t a[4][4], b[4][4];
#pragma unroll
            for (int mf = 0; mf < 4; mf++) {
                uint32_t ad = sA + (uint32_t)((wm * 64 + mf * 16 + aRow) * (PADK * 2) + (kk + aCol) * 2);
                LDSM4(a[mf][0], a[mf][1], a[mf][2], a[mf][3], ad);
            }
#pragma unroll
            for (int p = 0; p < 4; p++) {
                uint32_t bd = sB + (uint32_t)((wn * 64 + p * 16 + bRow) * (PADK * 2) + (kk + bCol) * 2);
                LDSM4(b[p][0], b[p][1], b[p][2], b[p][3], bd);
            }
#pragma unroll
            for (int mf = 0; mf < 4; mf++)
#pragma unroll
                for (int nf = 0; nf < 8; nf++)
                    MMA16816(acc[mf][nf], a[mf], b[nf >> 1][(nf & 1) * 2], b[nf >> 1][(nf & 1) * 2 + 1]);
        }
        __syncthreads();
    }
    CP_WAIT0();
}

// ---------------- GEMM1 + fused chunk-local scan ----------------
#define SCAN_STRIDE 264
#define SMEM_SCAN   (128 * SCAN_STRIDE * 4)   // 135168 B

__global__ __launch_bounds__(256, 1)
void gemm1_scan(const __half* __restrict__ A,
                const __half* __restrict__ B) {
    extern __shared__ char smem[];
    const uint32_t sb = smem_u32(smem);
    const int tid = threadIdx.x;
    const int wid = tid >> 5, lid = tid & 31;
    const int m0 = blockIdx.y * 128;
    const int n0 = blockIdx.x * 256;
    const int wm = wid >> 2, wn = wid & 3;

    float acc[4][8][4];
#pragma unroll
    for (int i = 0; i < 4; i++)
#pragma unroll
        for (int j = 0; j < 8; j++)
#pragma unroll
            for (int q = 0; q < 4; q++) acc[i][j][q] = 0.0f;

    gemm_mainloop(sb, A + (size_t)m0 * KCAT, B + (size_t)n0 * D_INP,
                  D_INP, KCAT, D_INP, acc, tid, wm, wn, lid);

    __syncthreads();            // pipeline smem dead, reuse for scan buffer

    float* sc = (float*)smem;   // [128][SCAN_STRIDE]
    const int gid = lid >> 2, tig = lid & 3;
#pragma unroll
    for (int mf = 0; mf < 4; mf++) {
        const int row = wm * 64 + mf * 16 + gid;
#pragma unroll
        for (int nf = 0; nf < 8; nf++) {
            const int col = wn * 64 + nf * 8 + tig * 2;
            *(float2*)(sc + row * SCAN_STRIDE + col) =
                make_float2(acc[mf][nf][0], acc[mf][nf][1]);
            *(float2*)(sc + (row + 8) * SCAN_STRIDE + col) =
                make_float2(acc[mf][nf][2], acc[mf][nf][3]);
        }
    }
    __syncthreads();

    // chunk-local complex scan: 128 complex pairs in this tile
    if (tid < 128) {
        const int np = (n0 >> 1) + tid;         // global state index
        const float2 lam = g_lam[np];
        const int b = m0 >> 12;                 // / T_LEN
        const int c = (m0 & (T_LEN - 1)) >> 7;  // / CHUNK
        float xr = 0.0f, xi = 0.0f;
        __half* out = g_A2 + (size_t)m0 * KCAT + 2 * np;
#pragma unroll 4
        for (int t = 0; t < CHUNK; t++) {
            float2 bu = *(const float2*)(sc + t * SCAN_STRIDE + 2 * tid);
            float nxr = fmaf(lam.x, xr, fmaf(-lam.y, xi, bu.x));
            float nxi = fmaf(lam.x, xi, fmaf(lam.y, xr, bu.y));
            xr = nxr; xi = nxi;
            *(__half2*)(out + (size_t)t * KCAT) = __floats2half2_rn(xr, xi);
        }
        g_F[(b * NCHUNK + c) * N_ST + np] = make_float2(xr, xi);
    }
}

// ---------------- GEMM2: y[M,256] = A2 @ W2^T, single n-tile ----------------
__global__ __launch_bounds__(256, 1)
void gemm2_out(const __half* __restrict__ A,
               const __half* __restrict__ B,
               float* __restrict__ C) {
    extern __shared__ char smem[];
    const uint32_t sb = smem_u32(smem);
    const int tid = threadIdx.x;
    const int wid = tid >> 5, lid = tid & 31;
    const int m0 = blockIdx.y * 128;
    const int wm = wid >> 2, wn = wid & 3;

    float acc[4][8][4];
#pragma unroll
    for (int i = 0; i < 4; i++)
#pragma unroll
        for (int j = 0; j < 8; j++)
#pragma unroll
            for (int q = 0; q < 4; q++) acc[i][j][q] = 0.0f;

    gemm_mainloop(sb, A + (size_t)m0 * KCAT, B,
                  KCAT, KCAT, KCAT, acc, tid, wm, wn, lid);

    const int gid = lid >> 2, tig = lid & 3;
#pragma unroll
    for (int mf = 0; mf < 4; mf++) {
        const int row = m0 + wm * 64 + mf * 16 + gid;
#pragma unroll
        for (int nf = 0; nf < 8; nf++) {
            const int col = wn * 64 + nf * 8 + tig * 2;
            *(float2*)(C + (size_t)row * D_OUTP + col) =
                make_float2(acc[mf][nf][0], acc[mf][nf][1]);
            *(float2*)(C + (size_t)(row + 8) * D_OUTP + col) =
                make_float2(acc[mf][nf][2], acc[mf][nf][3]);
        }
    }
}

// ---------------- chunk-level prefix over finals ----------------
__global__ void k_chunk_prefix() {
    int id = blockIdx.x * blockDim.x + threadIdx.x;
    if (id >= B_SZ * N_ST) return;
    int n = id & (N_ST - 1);
    int b = id >> 9;
    float2 lamL = g_lamL[n];
    float sr = 0.0f, si = 0.0f;
#pragma unroll
    for (int c = 0; c < NCHUNK; c++) {
        int idx = (b * NCHUNK + c) * N_ST + n;
        g_carry[idx] = make_float2(sr, si);
        float2 f = g_F[idx];
        float nsr = fmaf(lamL.x, sr, fmaf(-lamL.y, si, f.x));
        float nsi = fmaf(lamL.x, si, fmaf(lamL.y, sr, f.y));
        sr = nsr; si = nsi;
    }
}

// ---------------- carry correction: x_t += lam^{t+1} * carry ----------------
__global__ void k_correct() {
    int id = blockIdx.x * blockDim.x + threadIdx.x;
    if (id >= B_SZ * NCHUNK * N_ST) return;
    int np = id & (N_ST - 1);
    int c = (id >> 9) & (NCHUNK - 1);
    int b = id >> 14;
    if (c == 0) return;                       // carry is zero for chunk 0
    float2 carry = g_carry[id];
    float2 lam = g_lam[np];
    float fr = carry.x, fi = carry.y;
    __half* xp = g_A2 + ((size_t)(b * T_LEN + c * CHUNK)) * KCAT + 2 * np;
#pragma unroll 4
    for (int t = 0; t < CHUNK; t++) {
        float nfr = fr * lam.x - fi * lam.y;
        float nfi = fr * lam.y + fi * lam.x;
        fr = nfr; fi = nfi;
        __half2 v = *(__half2*)(xp + (size_t)t * KCAT);
        float2 xv = __half22float2(v);
        *(__half2*)(xp + (size_t)t * KCAT) =
            __floats2half2_rn(xv.x + fr, xv.y + fi);
    }
}

// ---------------- launch ----------------
extern "C" void kernel_launch(void* const* d_in, const int* in_sizes, int n_in,
                              void* d_out, int out_size) {
    const float* u_in      = (const float*)d_in[0];
    const float* nu_log    = (const float*)d_in[1];
    const float* theta_log = (const float*)d_in[2];
    const float* gamma_log = (const float*)d_in[3];
    const float* B_real    = (const float*)d_in[4];
    const float* B_imag    = (const float*)d_in[5];
    const float* C_real    = (const float*)d_in[6];
    const float* C_imag    = (const float*)d_in[7];
    const float* Dm        = (const float*)d_in[8];
    float* y = (float*)d_out;

    __half *a2, *b1, *w2;
    cudaGetSymbolAddress((void**)&a2, g_A2);
    cudaGetSymbolAddress((void**)&b1, g_B1);
    cudaGetSymbolAddress((void**)&w2, g_W2);

    cudaFuncSetAttribute(gemm1_scan,
                         cudaFuncAttributeMaxDynamicSharedMemorySize, SMEM_SCAN);
    cudaFuncSetAttribute(gemm2_out,
                         cudaFuncAttributeMaxDynamicSharedMemorySize, SMEM_GEMM);

    // setup / conversions
    k_setup<<<2, 256>>>(nu_log, theta_log);
    k_cvtB<<<(NBU * D_INP + 255) / 256, 256>>>(gamma_log, B_real, B_imag);
    k_buildW2<<<(D_OUTP * KCAT + 255) / 256, 256>>>(C_real, C_imag, Dm);
    k_cvtU<<<(M_TOT * D_INP / 2 + 255) / 256, 256>>>(u_in);

    // GEMM1 + chunk-local scan: writes X_local (fp16) into A2 and chunk finals
    {
        dim3 grid(NBU / 256, M_TOT / 128);
        gemm1_scan<<<grid, 256, SMEM_SCAN>>>(a2 + NBU, b1);
    }

    // chunk prefix + carry correction
    k_chunk_prefix<<<(B_SZ * N_ST + 255) / 256, 256>>>();
    k_correct<<<(B_SZ * NCHUNK * N_ST + 255) / 256, 256>>>();

    // GEMM 2: y[M, 256] = [X | u] @ W2^T, K=1280, single n-tile
    {
        dim3 grid(1, M_TOT / 128);
        gemm2_out<<<grid, 256, SMEM_GEMM>>>(a2, w2, y);
    }
}